// round 13
// baseline (speedup 1.0000x reference)
#include <cuda_runtime.h>
#include <cuda_bf16.h>
#include <cstdint>
#include <math.h>

#define Bc 64
#define Wc 16
#define Tc 64
#define Uc 128
#define Sc 20
#define Nc 8
#define INF_ 100000.0f

// ---------------- scratch ----------------
__device__ float g_qslot[Bc*Wc*Sc*Uc];
__device__ float g_qw[Bc*Wc*Sc*Uc];
__device__ float g_qslotW1[Bc*Wc*Sc*Uc];
__device__ float g_qsW[Bc*Wc*Nc*Uc];
__device__ float g_logits[Bc*Wc*Sc*Nc];
// W2^T bf16 hi/lo, packed row-major [feat=128][k=128]
__device__ __align__(16) __nv_bfloat16 g_W2Thi[16384];
__device__ __align__(16) __nv_bfloat16 g_W2Tlo[16384];
// qstatus bf16 hi/lo, packed [b][r=128][k=128]
__device__ __align__(16) __nv_bfloat16 g_QShi[Bc*128*128];
__device__ __align__(16) __nv_bfloat16 g_QSlo[Bc*128*128];

// packed f32x2 FMA
__device__ __forceinline__ float2 pfma2(float2 a, float2 b, float2 c) {
    unsigned long long ua = *reinterpret_cast<unsigned long long*>(&a);
    unsigned long long ub = *reinterpret_cast<unsigned long long*>(&b);
    unsigned long long uc = *reinterpret_cast<unsigned long long*>(&c);
    unsigned long long ud;
    asm("fma.rn.f32x2 %0, %1, %2, %3;" : "=l"(ud) : "l"(ua), "l"(ub), "l"(uc));
    return *reinterpret_cast<float2*>(&ud);
}

__device__ __forceinline__ unsigned smem_u32_of(const void* p) {
    unsigned a;
    asm("{ .reg .u64 t; cvta.to.shared.u64 t, %1; cvt.u32.u64 %0, t; }" : "=r"(a) : "l"(p));
    return a;
}

// warp-level bf16 MMA (baseline PTX, legal on compute_103)
__device__ __forceinline__ void mma16816(float* d, const unsigned* a, const unsigned* b) {
    asm volatile(
        "mma.sync.aligned.m16n8k16.row.col.f32.bf16.bf16.f32 "
        "{%0,%1,%2,%3}, {%4,%5,%6,%7}, {%8,%9}, {%0,%1,%2,%3};"
        : "+f"(d[0]), "+f"(d[1]), "+f"(d[2]), "+f"(d[3])
        : "r"(a[0]), "r"(a[1]), "r"(a[2]), "r"(a[3]), "r"(b[0]), "r"(b[1]));
}

__device__ __forceinline__ void ldsm_x4(unsigned* r, unsigned addr) {
    asm volatile("ldmatrix.sync.aligned.m8n8.x4.shared.b16 {%0,%1,%2,%3}, [%4];"
        : "=r"(r[0]), "=r"(r[1]), "=r"(r[2]), "=r"(r[3]) : "r"(addr));
}

// ---------------- kernel 1: utterance attention -> q_slot + W2^T bf16 prep fold-in ----------------
#define QP 132
#define Q_SMEM ((Tc*QP + Sc*QP + Sc*Tc) * 4)
__global__ __launch_bounds__(256) void qslot_kernel(
    const float* __restrict__ h, const float* __restrict__ c,
    const float* __restrict__ pos, float* __restrict__ qslot,
    const float* __restrict__ W2)
{
    extern __shared__ float qs[];
    float* h_sh = qs;
    float* c_sh = qs + Tc*QP;
    float* p_sh = qs + Tc*QP + Sc*QP;

    int bw  = blockIdx.x;
    int tid = threadIdx.x;

    if (bw < 64) {
        int idx = bw * 256 + tid;
        int f = idx >> 7, k = idx & 127;
        float val = W2[(size_t)k * 128 + f];
        __nv_bfloat16 vhi = __float2bfloat16(val);
        __nv_bfloat16 vlo = __float2bfloat16(val - __bfloat162float(vhi));
        g_W2Thi[idx] = vhi;
        g_W2Tlo[idx] = vlo;
    }

    const float4* hb = (const float4*)(h + (size_t)bw * Tc * Uc);
    for (int i = tid; i < Tc*32; i += 256) {
        int r = i >> 5, c4 = i & 31;
        *(float4*)(h_sh + r*QP + 4*c4) = hb[i];
    }
    const float4* cg = (const float4*)c;
    for (int i = tid; i < Sc*32; i += 256) {
        int r = i >> 5, c4 = i & 31;
        *(float4*)(c_sh + r*QP + 4*c4) = cg[i];
    }
    __syncthreads();

    for (int task = tid; task < 320; task += 256) {
        int t = task & 63, sg = task >> 6;
        const float4* hr = (const float4*)(h_sh + t*QP);
        float2 pa[4];
        #pragma unroll
        for (int i = 0; i < 4; i++) pa[i] = make_float2(0.f, 0.f);
        #pragma unroll 8
        for (int u4 = 0; u4 < 32; u4++) {
            float4 hv = hr[u4];
            float2 hl = make_float2(hv.x, hv.y);
            float2 hh = make_float2(hv.z, hv.w);
            #pragma unroll
            for (int i = 0; i < 4; i++) {
                float4 cv = *(const float4*)(c_sh + (4*sg+i)*QP + 4*u4);
                pa[i] = pfma2(make_float2(cv.x, cv.y), hl, pa[i]);
                pa[i] = pfma2(make_float2(cv.z, cv.w), hh, pa[i]);
            }
        }
        #pragma unroll
        for (int i = 0; i < 4; i++)
            p_sh[(4*sg+i)*Tc + t] = pa[i].x + pa[i].y;
    }
    __syncthreads();

    if (tid < Sc) {
        float* pr = p_sh + tid * Tc;
        float m = -3.4e38f;
        #pragma unroll
        for (int t = 0; t < Tc; t++) {
            float v = pr[t];
            if (v == 0.f) v = -INF_;
            pr[t] = v;
            m = fmaxf(m, v);
        }
        float sum = 0.f;
        #pragma unroll
        for (int t = 0; t < Tc; t++) { float e = expf(pr[t] - m); pr[t] = e; sum += e; }
        float r = 1.f / sum;
        #pragma unroll
        for (int t = 0; t < Tc; t++) pr[t] *= r;
    }
    __syncthreads();

    if (tid < 160) {
        int u4 = tid & 31, sg = tid >> 5;
        float2 aL[4], aH[4];
        #pragma unroll
        for (int i = 0; i < 4; i++) { aL[i] = make_float2(0.f, 0.f); aH[i] = make_float2(0.f, 0.f); }
        #pragma unroll 4
        for (int t = 0; t < Tc; t++) {
            float4 hv = *(const float4*)(h_sh + t*QP + 4*u4);
            float2 hl = make_float2(hv.x, hv.y);
            float2 hh = make_float2(hv.z, hv.w);
            #pragma unroll
            for (int i = 0; i < 4; i++) {
                float p = p_sh[(4*sg+i)*Tc + t];
                float2 pp = make_float2(p, p);
                aL[i] = pfma2(pp, hl, aL[i]);
                aH[i] = pfma2(pp, hh, aH[i]);
            }
        }
        const float* posb = pos + (size_t)bw * Sc * Uc;
        float* qb = qslot + (size_t)bw * Sc * Uc;
        #pragma unroll
        for (int i = 0; i < 4; i++) {
            int s = 4*sg + i;
            float4 pv = *(const float4*)(posb + s*128 + 4*u4);
            float4 o;
            o.x = aL[i].x + pv.x; o.y = aL[i].y + pv.y;
            o.z = aH[i].x + pv.z; o.w = aH[i].y + pv.w;
            *(float4*)(qb + s*128 + 4*u4) = o;
        }
    }
}

// ---------------- dual-output GEMM (proven) ----------------
#define DA_PITCH 34
__global__ __launch_bounds__(256) void gemm_dual_kernel(
    const float* __restrict__ A,
    const float* __restrict__ Wa, const float* __restrict__ Wb,
    const float* __restrict__ biasB,
    float* __restrict__ Ca, float* __restrict__ Cb)
{
    __shared__ float  A_sh[32*DA_PITCH];
    __shared__ float2 Wi[2*16*128];

    int tid  = threadIdx.x;
    int row0 = blockIdx.x * 32;
    int tx = tid & 31, ty = tid >> 5;
    int c0 = tx * 4;
    int r0 = ty * 4;

    float2 dacc[2][4][4];
    #pragma unroll
    for (int m = 0; m < 2; m++)
        #pragma unroll
        for (int r = 0; r < 4; r++)
            #pragma unroll
            for (int cc = 0; cc < 4; cc++) dacc[m][r][cc] = make_float2(0.f, 0.f);

    for (int k0 = 0; k0 < 128; k0 += 32) {
        __syncthreads();
        #pragma unroll
        for (int i = 0; i < 4; i++) {
            int r = ty + 8*i;
            A_sh[r*DA_PITCH + tx] = A[(size_t)(row0 + r) * 128 + k0 + tx];
        }
        #pragma unroll
        for (int i = 0; i < 16; i++) {
            int idx = tid + 256*i;
            int m = idx >> 11, kp = (idx >> 7) & 15, cc = idx & 127;
            const float* W = m ? Wb : Wa;
            Wi[idx] = make_float2(W[(size_t)(k0 + 2*kp) * 128 + cc],
                                  W[(size_t)(k0 + 2*kp + 1) * 128 + cc]);
        }
        __syncthreads();

        #pragma unroll 4
        for (int kp = 0; kp < 16; kp++) {
            float2 ar[4];
            #pragma unroll
            for (int r = 0; r < 4; r++)
                ar[r] = *(const float2*)(A_sh + (r0 + r)*DA_PITCH + 2*kp);

            float2 uwa[4], uwb[4];
            {
                const float4* wa4 = (const float4*)(Wi + kp*128 + c0);
                const float4* wb4 = (const float4*)(Wi + 2048 + kp*128 + c0);
                float4 waA = wa4[0];
                float4 waB = wa4[1];
                float4 wbA = wb4[0];
                float4 wbB = wb4[1];
                uwa[0] = make_float2(waA.x, waA.y);
                uwa[1] = make_float2(waA.z, waA.w);
                uwa[2] = make_float2(waB.x, waB.y);
                uwa[3] = make_float2(waB.z, waB.w);
                uwb[0] = make_float2(wbA.x, wbA.y);
                uwb[1] = make_float2(wbA.z, wbA.w);
                uwb[2] = make_float2(wbB.x, wbB.y);
                uwb[3] = make_float2(wbB.z, wbB.w);
            }

            #pragma unroll
            for (int r = 0; r < 4; r++) {
                #pragma unroll
                for (int cc = 0; cc < 4; cc++) {
                    dacc[0][r][cc] = pfma2(ar[r], uwa[cc], dacc[0][r][cc]);
                    dacc[1][r][cc] = pfma2(ar[r], uwb[cc], dacc[1][r][cc]);
                }
            }
        }
    }

    float bb[4];
    #pragma unroll
    for (int cc = 0; cc < 4; cc++) bb[cc] = biasB[c0 + cc];
    #pragma unroll
    for (int r = 0; r < 4; r++) {
        int row = row0 + r0 + r;
        float4 oa, ob;
        oa.x = dacc[0][r][0].x + dacc[0][r][0].y;
        oa.y = dacc[0][r][1].x + dacc[0][r][1].y;
        oa.z = dacc[0][r][2].x + dacc[0][r][2].y;
        oa.w = dacc[0][r][3].x + dacc[0][r][3].y;
        ob.x = dacc[1][r][0].x + dacc[1][r][0].y + bb[0];
        ob.y = dacc[1][r][1].x + dacc[1][r][1].y + bb[1];
        ob.z = dacc[1][r][2].x + dacc[1][r][2].y + bb[2];
        ob.w = dacc[1][r][3].x + dacc[1][r][3].y + bb[3];
        *(float4*)&Ca[(size_t)row*128 + c0] = oa;
        *(float4*)&Cb[(size_t)row*128 + c0] = ob;
    }
}

// ---------------- proven GEMM (qsW) + qstatus bf16 convert fold-in ----------------
__global__ __launch_bounds__(256) void gemm128_kernel(
    const float* __restrict__ A, const float* __restrict__ Wm,
    const float* __restrict__ bias, float* __restrict__ C,
    const float* __restrict__ qstatus)
{
    __shared__ float A_sh[32*33];
    __shared__ float W_sh[32*128];
    int tid  = threadIdx.x;
    int row0 = blockIdx.x * 32;
    int tx = tid & 31, ty = tid >> 5;
    int r0 = ty * 4, c0 = tx * 4;

    for (int i = blockIdx.x * 256 + tid; i < Bc*128*128; i += 256*256) {
        float v = qstatus[i];
        __nv_bfloat16 vhi = __float2bfloat16(v);
        __nv_bfloat16 vlo = __float2bfloat16(v - __bfloat162float(vhi));
        g_QShi[i] = vhi;
        g_QSlo[i] = vlo;
    }

    float2 gacc[4][2];
    #pragma unroll
    for (int r = 0; r < 4; r++) {
        gacc[r][0] = make_float2(0.f, 0.f);
        gacc[r][1] = make_float2(0.f, 0.f);
    }

    for (int k0 = 0; k0 < 128; k0 += 32) {
        __syncthreads();
        #pragma unroll
        for (int rr = 0; rr < 32; rr += 8) {
            int r = rr + ty;
            A_sh[tx*33 + r] = A[(size_t)(row0 + r) * 128 + k0 + tx];
        }
        for (int i = tid; i < 32*128; i += 256)
            W_sh[i] = Wm[(size_t)(k0 + (i >> 7)) * 128 + (i & 127)];
        __syncthreads();
        #pragma unroll
        for (int k = 0; k < 32; k++) {
            float4 w = *(const float4*)&W_sh[k*128 + c0];
            float2 wl = make_float2(w.x, w.y);
            float2 wh = make_float2(w.z, w.w);
            #pragma unroll
            for (int rr = 0; rr < 4; rr++) {
                float a = A_sh[k*33 + r0 + rr];
                float2 aa = make_float2(a, a);
                gacc[rr][0] = pfma2(aa, wl, gacc[rr][0]);
                gacc[rr][1] = pfma2(aa, wh, gacc[rr][1]);
            }
        }
    }
    float bb0 = bias ? bias[c0+0] : 0.f;
    float bb1 = bias ? bias[c0+1] : 0.f;
    float bb2 = bias ? bias[c0+2] : 0.f;
    float bb3 = bias ? bias[c0+3] : 0.f;
    #pragma unroll
    for (int rr = 0; rr < 4; rr++) {
        float4 o;
        o.x = gacc[rr][0].x + bb0; o.y = gacc[rr][0].y + bb1;
        o.z = gacc[rr][1].x + bb2; o.w = gacc[rr][1].y + bb3;
        *(float4*)&C[(size_t)(row0 + r0 + rr) * 128 + c0] = o;
    }
}

// ---------------- fused kernel: 1024 threads, B-frags direct from global ----------------
#define PITCHB 272
#define H1_HI  0
#define H1_LO  43520
#define QWB_HI 87040
#define QWB_LO 95744
#define CO_B   104448
#define P2_B   120832
#define BW_B   131072
#define F_BYTES 132096

__global__ __launch_bounds__(1024, 1) void fused_kernel(
    const float* __restrict__ qw, const float* __restrict__ q1,
    const float* __restrict__ qsw,
    const float* __restrict__ b2, const float* __restrict__ W3,
    const float* __restrict__ b3, float* __restrict__ logits)
{
    extern __shared__ float sm[];
    unsigned base_u = smem_u32_of(sm);
    char* basep = (char*)sm;

    float* p2_sh = (float*)(basep + P2_B);
    float* bw_sh = (float*)(basep + BW_B);
    float* co_sh = (float*)(basep + CO_B);   // 32 x 128 fp32

    int bw = blockIdx.x;
    int b  = bw >> 4;
    int tid = threadIdx.x;

    // ---- stage loads: qw -> bf16 hi/lo (rows 20-31 zero), b2|W3 ----
    {
        const float* qwb = qw + (size_t)bw * 2560;
        for (int i = tid; i < 2048; i += 1024) {
            int row = i >> 6, kp = i & 63;
            __nv_bfloat162 hp, lp;
            if (row < Sc) {
                float2 v = *(const float2*)(qwb + row * 128 + 2*kp);
                __nv_bfloat16 hx = __float2bfloat16(v.x);
                __nv_bfloat16 hy = __float2bfloat16(v.y);
                hp.x = hx; hp.y = hy;
                lp.x = __float2bfloat16(v.x - __bfloat162float(hx));
                lp.y = __float2bfloat16(v.y - __bfloat162float(hy));
            } else {
                hp.x = __float2bfloat16(0.f); hp.y = hp.x;
                lp.x = hp.x; lp.y = hp.x;
            }
            *(unsigned*)(basep + QWB_HI + row*PITCHB + kp*4) = *(unsigned*)&hp;
            *(unsigned*)(basep + QWB_LO + row*PITCHB + kp*4) = *(unsigned*)&lp;
        }
    }
    if (tid < 128) bw_sh[tid] = b2[tid];
    else if (tid < 256) bw_sh[tid] = W3[tid - 128];
    __syncthreads();

    // ---- co[20x128] = qw @ qstatus^T ; 32 warps = 2mt x 16np; B direct from global ----
    {
        int lane = tid & 31;
        int wrp  = tid >> 5;
        int mt   = wrp >> 4;                 // 0..1
        int np   = wrp & 15;                 // r-cols 8np..8np+7

        unsigned a_hi = base_u + (unsigned)(QWB_HI + (lane & 15) * PITCHB
                      + (lane >> 4) * 16 + mt * 16 * PITCHB);
        unsigned a_lo = a_hi + (unsigned)(QWB_LO - QWB_HI);

        const unsigned* qsh = (const unsigned*)(g_QShi + (size_t)b * 16384);
        const unsigned* qsl = (const unsigned*)(g_QSlo + (size_t)b * 16384);
        int rbase = (8*np + (lane >> 2)) * 64 + (lane & 3);

        float d[4] = {0.f, 0.f, 0.f, 0.f};
        #pragma unroll
        for (int ks = 0; ks < 8; ks++) {
            unsigned ah[4], al[4];
            ldsm_x4(ah, a_hi + ks*32);
            ldsm_x4(al, a_lo + ks*32);
            unsigned bh[2], bl[2];
            bh[0] = qsh[rbase + ks*8];
            bh[1] = qsh[rbase + ks*8 + 4];
            bl[0] = qsl[rbase + ks*8];
            bl[1] = qsl[rbase + ks*8 + 4];
            mma16816(d, ah, bh);
            mma16816(d, ah, bl);
            mma16816(d, al, bh);
            mma16816(d, al, bl);
        }
        int r0 = mt * 16 + (lane >> 2);
        int c0 = 8*np + 2*(lane & 3);
        co_sh[r0 * 128 + c0]           = d[0];
        co_sh[r0 * 128 + c0 + 1]       = d[1];
        co_sh[(r0 + 8) * 128 + c0]     = d[2];
        co_sh[(r0 + 8) * 128 + c0 + 1] = d[3];
    }
    __syncthreads();

    // ---- masked softmax over x per (s,n); p2 as [n][s][x] ----
    if (tid < Sc * Nc) {
        int s = tid >> 3, n = tid & 7;
        float vals[16];
        float m = -3.4e38f;
        #pragma unroll
        for (int x = 0; x < 16; x++) {
            float v = co_sh[s * 128 + x * 8 + n];
            if (v == 0.f) v = -INF_;
            vals[x] = v;
            m = fmaxf(m, v);
        }
        float sum = 0.f;
        #pragma unroll
        for (int x = 0; x < 16; x++) { float e = expf(vals[x] - m); vals[x] = e; sum += e; }
        float rs = 1.f / sum;
        #pragma unroll
        for (int x = 0; x < 16; x++)
            p2_sh[n * 320 + s * 16 + x] = vals[x] * rs;
    }
    __syncthreads();

    // ---- layer1 -> bf16 hi/lo h1 images; 1024 threads: (n, s-half, u2) ----
    {
        int n  = tid >> 7;                  // 0..7
        int sh = (tid >> 6) & 1;            // s half
        int u2 = tid & 63;
        const float* qswb = qsw + ((size_t)b * Wc * Nc + n) * Uc + 2 * u2;
        float2 qv[16];
        #pragma unroll
        for (int x = 0; x < 16; x++)
            qv[x] = *(const float2*)(qswb + (size_t)x * Nc * Uc);

        const float* q1b = q1 + (size_t)bw * 2560;
        const float4* pp_base = (const float4*)(p2_sh + n * 320);
        char* hhi = basep + H1_HI;
        char* hlo = basep + H1_LO;

        #pragma unroll
        for (int si = 0; si < 10; si++) {
            int s = sh * 10 + si;
            float4 p0 = pp_base[s*4 + 0];
            float4 p1 = pp_base[s*4 + 1];
            float4 p2v = pp_base[s*4 + 2];
            float4 p3 = pp_base[s*4 + 3];
            float2 a = make_float2(0.f, 0.f);
            a = pfma2(make_float2(p0.x, p0.x), qv[0],  a);
            a = pfma2(make_float2(p0.y, p0.y), qv[1],  a);
            a = pfma2(make_float2(p0.z, p0.z), qv[2],  a);
            a = pfma2(make_float2(p0.w, p0.w), qv[3],  a);
            a = pfma2(make_float2(p1.x, p1.x), qv[4],  a);
            a = pfma2(make_float2(p1.y, p1.y), qv[5],  a);
            a = pfma2(make_float2(p1.z, p1.z), qv[6],  a);
            a = pfma2(make_float2(p1.w, p1.w), qv[7],  a);
            a = pfma2(make_float2(p2v.x, p2v.x), qv[8],  a);
            a = pfma2(make_float2(p2v.y, p2v.y), qv[9],  a);
            a = pfma2(make_float2(p2v.z, p2v.z), qv[10], a);
            a = pfma2(make_float2(p2v.w, p2v.w), qv[11], a);
            a = pfma2(make_float2(p3.x, p3.x), qv[12], a);
            a = pfma2(make_float2(p3.y, p3.y), qv[13], a);
            a = pfma2(make_float2(p3.z, p3.z), qv[14], a);
            a = pfma2(make_float2(p3.w, p3.w), qv[15], a);

            float2 base = *(const float2*)(q1b + s * 128 + 2 * u2);
            float hx = fmaxf(a.x + base.x, 0.f);
            float hy = fmaxf(a.y + base.y, 0.f);

            __nv_bfloat16 bhx = __float2bfloat16(hx);
            __nv_bfloat16 bhy = __float2bfloat16(hy);
            __nv_bfloat16 blx = __float2bfloat16(hx - __bfloat162float(bhx));
            __nv_bfloat16 bly = __float2bfloat16(hy - __bfloat162float(bhy));
            __nv_bfloat162 hp;
            hp.x = bhx; hp.y = bhy;
            __nv_bfloat162 lp;
            lp.x = blx; lp.y = bly;

            int row = s * 8 + n;
            *(unsigned*)(hhi + row*PITCHB + u2*4) = *(unsigned*)&hp;
            *(unsigned*)(hlo + row*PITCHB + u2*4) = *(unsigned*)&lp;
        }
    }
    __syncthreads();

    // ---- layer2: 32 warps = 4 m-groups {3,3,2,2} x 8 n-pairs; B direct from global ----
    {
        int lane = tid & 31;
        int wrp  = tid >> 5;
        int g    = wrp >> 3;                 // 0..3
        int p    = wrp & 7;                  // feats 16p..16p+15
        int mcnt = (g < 2) ? 3 : 2;
        int mst  = (g < 2) ? 3*g : 6 + 2*(g - 2);

        const unsigned* wth = (const unsigned*)g_W2Thi;
        const unsigned* wtl = (const unsigned*)g_W2Tlo;
        int fb0 = (16*p + 0 + (lane >> 2)) * 64 + (lane & 3);
        int fb1 = (16*p + 8 + (lane >> 2)) * 64 + (lane & 3);

        unsigned abase_hi = base_u + (unsigned)(H1_HI + (lane & 15) * PITCHB + (lane >> 4) * 16);
        unsigned abase_lo = abase_hi + (unsigned)(H1_LO - H1_HI);
        float* part_sh = p2_sh;              // alias: p2 dead

        float d[3][2][4];
        #pragma unroll
        for (int mi = 0; mi < 3; mi++)
            #pragma unroll
            for (int nt = 0; nt < 2; nt++)
                #pragma unroll
                for (int j = 0; j < 4; j++) d[mi][nt][j] = 0.f;

        #pragma unroll
        for (int ks = 0; ks < 8; ks++) {
            unsigned bh[2][2], bl[2][2];
            bh[0][0] = wth[fb0 + ks*8];
            bh[0][1] = wth[fb0 + ks*8 + 4];
            bh[1][0] = wth[fb1 + ks*8];
            bh[1][1] = wth[fb1 + ks*8 + 4];
            bl[0][0] = wtl[fb0 + ks*8];
            bl[0][1] = wtl[fb0 + ks*8 + 4];
            bl[1][0] = wtl[fb1 + ks*8];
            bl[1][1] = wtl[fb1 + ks*8 + 4];
            #pragma unroll
            for (int mi = 0; mi < 3; mi++) {
                if (mi < mcnt) {
                    int mt = mst + mi;
                    unsigned ah[4], alr[4];
                    ldsm_x4(ah,  abase_hi + (unsigned)(mt * 16 * PITCHB) + ks*32);
                    ldsm_x4(alr, abase_lo + (unsigned)(mt * 16 * PITCHB) + ks*32);
                    #pragma unroll
                    for (int nt = 0; nt < 2; nt++) {
                        mma16816(d[mi][nt], ah,  bh[nt]);
                        mma16816(d[mi][nt], ah,  bl[nt]);
                        mma16816(d[mi][nt], alr, bh[nt]);
                    }
                }
            }
        }

        float b2c[2][2], w3c[2][2];
        #pragma unroll
        for (int nt = 0; nt < 2; nt++) {
            int c0 = 16*p + 8*nt + 2*(lane & 3);
            b2c[nt][0] = bw_sh[c0];       b2c[nt][1] = bw_sh[c0+1];
            w3c[nt][0] = bw_sh[128+c0];   w3c[nt][1] = bw_sh[128+c0+1];
        }

        #pragma unroll
        for (int mi = 0; mi < 3; mi++) {
            if (mi < mcnt) {
                int mt = mst + mi;
                float v0 = 0.f, v1 = 0.f;
                #pragma unroll
                for (int nt = 0; nt < 2; nt++) {
                    v0 += fmaxf(d[mi][nt][0] + b2c[nt][0], 0.f) * w3c[nt][0]
                        + fmaxf(d[mi][nt][1] + b2c[nt][1], 0.f) * w3c[nt][1];
                    v1 += fmaxf(d[mi][nt][2] + b2c[nt][0], 0.f) * w3c[nt][0]
                        + fmaxf(d[mi][nt][3] + b2c[nt][1], 0.f) * w3c[nt][1];
                }
                v0 += __shfl_xor_sync(0xffffffffu, v0, 1);
                v0 += __shfl_xor_sync(0xffffffffu, v0, 2);
                v1 += __shfl_xor_sync(0xffffffffu, v1, 1);
                v1 += __shfl_xor_sync(0xffffffffu, v1, 2);
                if ((lane & 3) == 0) {
                    int r0 = mt * 16 + (lane >> 2);
                    part_sh[r0 * 8 + p]       = v0;
                    part_sh[(r0 + 8) * 8 + p] = v1;
                }
            }
        }
    }
    __syncthreads();

    if (tid < 160) {
        const float4* pr = (const float4*)(p2_sh + tid * 8);
        float4 u = pr[0], v = pr[1];
        logits[(size_t)bw * 160 + tid] =
            u.x + u.y + u.z + u.w + v.x + v.y + v.z + v.w + b3[0];
    }
}

// ---------------- finalize ----------------
__global__ __launch_bounds__(160) void finalize_kernel(
    const float* __restrict__ logits, const float* __restrict__ mask,
    float* __restrict__ out, int scalar_idx, int logits_off)
{
    int b = blockIdx.x;
    int k = threadIdx.x;
    float m = -3.4e38f;
    #pragma unroll
    for (int w = 0; w < Wc; w++) {
        size_t idx = (size_t)(b*Wc + w) * (Sc*Nc) + k;
        float v = logits[idx] + mask[idx];
        m = fmaxf(m, v);
    }
    out[b*(Sc*Nc) + k] = (m > 0.f) ? 1.f : 0.f;
    out[(size_t)logits_off + b*(Sc*Nc) + k] = m;
    if (b == 0 && k == 0 && scalar_idx >= 0) out[scalar_idx] = 160.0f;
}

// ---------------- host launcher ----------------
extern "C" void kernel_launch(void* const* d_in, const int* in_sizes, int n_in,
                              void* d_out, int out_size)
{
    const float* h    = (const float*)d_in[0];
    const float* c    = (const float*)d_in[1];
    const float* pos  = (const float*)d_in[3];
    const float* qst  = (const float*)d_in[4];
    const float* mask = (const float*)d_in[5];
    const float* wgt  = (const float*)d_in[6];
    const float* W1   = (const float*)d_in[7];
    const float* b1   = (const float*)d_in[8];
    const float* W2   = (const float*)d_in[9];
    const float* b2   = (const float*)d_in[10];
    const float* W3   = (const float*)d_in[11];
    const float* b3   = (const float*)d_in[12];
    float* out = (float*)d_out;

    float *qslot_p, *qw_p, *qslotw1_p, *qsw_p, *logits_p;
    cudaGetSymbolAddress((void**)&qslot_p,   g_qslot);
    cudaGetSymbolAddress((void**)&qw_p,      g_qw);
    cudaGetSymbolAddress((void**)&qslotw1_p, g_qslotW1);
    cudaGetSymbolAddress((void**)&qsw_p,     g_qsW);
    cudaGetSymbolAddress((void**)&logits_p,  g_logits);

    const int M_qs = Bc*Wc*Sc;   // 20480
    const int M_st = Bc*Wc*Nc;   // 8192

    cudaFuncSetAttribute(qslot_kernel,
        cudaFuncAttributeMaxDynamicSharedMemorySize, Q_SMEM);
    cudaFuncSetAttribute(fused_kernel,
        cudaFuncAttributeMaxDynamicSharedMemorySize, F_BYTES);

    // fused stays at launch slot 4 (the profiled slot)
    gemm128_kernel<<<M_st/32, 256>>>(qst, W1 + 128*128, nullptr, qsw_p, qst);  // 1 (+ QS bf16 prep)
    qslot_kernel<<<Bc*Wc, 256, Q_SMEM>>>(h, c, pos, qslot_p, W2);              // 2 (+ W2^T bf16 prep)
    gemm_dual_kernel<<<M_qs/32, 256>>>(qslot_p, wgt, W1, b1, qw_p, qslotw1_p); // 3
    fused_kernel<<<Bc*Wc, 1024, F_BYTES>>>(                                    // 4  <-- profiled
        qw_p, qslotw1_p, qsw_p, b2, W3, b3, logits_p);

    int scalar_idx = (out_size == 2*Bc*Sc*Nc + 1) ? Bc*Sc*Nc : -1;
    int logits_off = out_size - Bc*Sc*Nc;
    finalize_kernel<<<Bc, 160>>>(logits_p, mask, out, scalar_idx, logits_off); // 5
}

// round 14
// speedup vs baseline: 1.2756x; 1.2756x over previous
#include <cuda_runtime.h>
#include <cuda_bf16.h>
#include <cstdint>
#include <math.h>

#define Bc 64
#define Wc 16
#define Tc 64
#define Uc 128
#define Sc 20
#define Nc 8
#define INF_ 100000.0f

// ---------------- scratch ----------------
__device__ float g_qslot[Bc*Wc*Sc*Uc];
__device__ float g_qw[Bc*Wc*Sc*Uc];
__device__ float g_qslotW1[Bc*Wc*Sc*Uc];
__device__ float g_qsW[Bc*Wc*Nc*Uc];
__device__ float g_logits[Bc*Wc*Sc*Nc];
__device__ __align__(16) __nv_bfloat16 g_W2Thi[16384];
__device__ __align__(16) __nv_bfloat16 g_W2Tlo[16384];
__device__ __align__(16) __nv_bfloat16 g_QShi[Bc*128*128];
__device__ __align__(16) __nv_bfloat16 g_QSlo[Bc*128*128];

__device__ __forceinline__ float2 pfma2(float2 a, float2 b, float2 c) {
    unsigned long long ua = *reinterpret_cast<unsigned long long*>(&a);
    unsigned long long ub = *reinterpret_cast<unsigned long long*>(&b);
    unsigned long long uc = *reinterpret_cast<unsigned long long*>(&c);
    unsigned long long ud;
    asm("fma.rn.f32x2 %0, %1, %2, %3;" : "=l"(ud) : "l"(ua), "l"(ub), "l"(uc));
    return *reinterpret_cast<float2*>(&ud);
}

__device__ __forceinline__ unsigned smem_u32_of(const void* p) {
    unsigned a;
    asm("{ .reg .u64 t; cvta.to.shared.u64 t, %1; cvt.u32.u64 %0, t; }" : "=r"(a) : "l"(p));
    return a;
}

__device__ __forceinline__ void mma16816(float* d, const unsigned* a, const unsigned* b) {
    asm volatile(
        "mma.sync.aligned.m16n8k16.row.col.f32.bf16.bf16.f32 "
        "{%0,%1,%2,%3}, {%4,%5,%6,%7}, {%8,%9}, {%0,%1,%2,%3};"
        : "+f"(d[0]), "+f"(d[1]), "+f"(d[2]), "+f"(d[3])
        : "r"(a[0]), "r"(a[1]), "r"(a[2]), "r"(a[3]), "r"(b[0]), "r"(b[1]));
}

__device__ __forceinline__ void ldsm_x4(unsigned* r, unsigned addr) {
    asm volatile("ldmatrix.sync.aligned.m8n8.x4.shared.b16 {%0,%1,%2,%3}, [%4];"
        : "=r"(r[0]), "=r"(r[1]), "=r"(r[2]), "=r"(r[3]) : "r"(addr));
}
__device__ __forceinline__ void ldsm_x2(unsigned* r, unsigned addr) {
    asm volatile("ldmatrix.sync.aligned.m8n8.x2.shared.b16 {%0,%1}, [%2];"
        : "=r"(r[0]), "=r"(r[1]) : "r"(addr));
}

// ---------------- kernel 1: utterance attention -> q_slot + W2^T bf16 prep fold-in ----------------
#define QP 132
#define Q_SMEM ((Tc*QP + Sc*QP + Sc*Tc) * 4)
__global__ __launch_bounds__(256) void qslot_kernel(
    const float* __restrict__ h, const float* __restrict__ c,
    const float* __restrict__ pos, float* __restrict__ qslot,
    const float* __restrict__ W2)
{
    extern __shared__ float qs[];
    float* h_sh = qs;
    float* c_sh = qs + Tc*QP;
    float* p_sh = qs + Tc*QP + Sc*QP;

    int bw  = blockIdx.x;
    int tid = threadIdx.x;

    if (bw < 64) {
        int idx = bw * 256 + tid;
        int f = idx >> 7, k = idx & 127;
        float val = W2[(size_t)k * 128 + f];
        __nv_bfloat16 vhi = __float2bfloat16(val);
        __nv_bfloat16 vlo = __float2bfloat16(val - __bfloat162float(vhi));
        g_W2Thi[idx] = vhi;
        g_W2Tlo[idx] = vlo;
    }

    const float4* hb = (const float4*)(h + (size_t)bw * Tc * Uc);
    for (int i = tid; i < Tc*32; i += 256) {
        int r = i >> 5, c4 = i & 31;
        *(float4*)(h_sh + r*QP + 4*c4) = hb[i];
    }
    const float4* cg = (const float4*)c;
    for (int i = tid; i < Sc*32; i += 256) {
        int r = i >> 5, c4 = i & 31;
        *(float4*)(c_sh + r*QP + 4*c4) = cg[i];
    }
    __syncthreads();

    for (int task = tid; task < 320; task += 256) {
        int t = task & 63, sg = task >> 6;
        const float4* hr = (const float4*)(h_sh + t*QP);
        float2 pa[4];
        #pragma unroll
        for (int i = 0; i < 4; i++) pa[i] = make_float2(0.f, 0.f);
        #pragma unroll 8
        for (int u4 = 0; u4 < 32; u4++) {
            float4 hv = hr[u4];
            float2 hl = make_float2(hv.x, hv.y);
            float2 hh = make_float2(hv.z, hv.w);
            #pragma unroll
            for (int i = 0; i < 4; i++) {
                float4 cv = *(const float4*)(c_sh + (4*sg+i)*QP + 4*u4);
                pa[i] = pfma2(make_float2(cv.x, cv.y), hl, pa[i]);
                pa[i] = pfma2(make_float2(cv.z, cv.w), hh, pa[i]);
            }
        }
        #pragma unroll
        for (int i = 0; i < 4; i++)
            p_sh[(4*sg+i)*Tc + t] = pa[i].x + pa[i].y;
    }
    __syncthreads();

    if (tid < Sc) {
        float* pr = p_sh + tid * Tc;
        float m = -3.4e38f;
        #pragma unroll
        for (int t = 0; t < Tc; t++) {
            float v = pr[t];
            if (v == 0.f) v = -INF_;
            pr[t] = v;
            m = fmaxf(m, v);
        }
        float sum = 0.f;
        #pragma unroll
        for (int t = 0; t < Tc; t++) { float e = expf(pr[t] - m); pr[t] = e; sum += e; }
        float r = 1.f / sum;
        #pragma unroll
        for (int t = 0; t < Tc; t++) pr[t] *= r;
    }
    __syncthreads();

    if (tid < 160) {
        int u4 = tid & 31, sg = tid >> 5;
        float2 aL[4], aH[4];
        #pragma unroll
        for (int i = 0; i < 4; i++) { aL[i] = make_float2(0.f, 0.f); aH[i] = make_float2(0.f, 0.f); }
        #pragma unroll 4
        for (int t = 0; t < Tc; t++) {
            float4 hv = *(const float4*)(h_sh + t*QP + 4*u4);
            float2 hl = make_float2(hv.x, hv.y);
            float2 hh = make_float2(hv.z, hv.w);
            #pragma unroll
            for (int i = 0; i < 4; i++) {
                float p = p_sh[(4*sg+i)*Tc + t];
                float2 pp = make_float2(p, p);
                aL[i] = pfma2(pp, hl, aL[i]);
                aH[i] = pfma2(pp, hh, aH[i]);
            }
        }
        const float* posb = pos + (size_t)bw * Sc * Uc;
        float* qb = qslot + (size_t)bw * Sc * Uc;
        #pragma unroll
        for (int i = 0; i < 4; i++) {
            int s = 4*sg + i;
            float4 pv = *(const float4*)(posb + s*128 + 4*u4);
            float4 o;
            o.x = aL[i].x + pv.x; o.y = aL[i].y + pv.y;
            o.z = aH[i].x + pv.z; o.w = aH[i].y + pv.w;
            *(float4*)(qb + s*128 + 4*u4) = o;
        }
    }
}

// ---------------- dual-output GEMM (proven) ----------------
#define DA_PITCH 34
__global__ __launch_bounds__(256) void gemm_dual_kernel(
    const float* __restrict__ A,
    const float* __restrict__ Wa, const float* __restrict__ Wb,
    const float* __restrict__ biasB,
    float* __restrict__ Ca, float* __restrict__ Cb)
{
    __shared__ float  A_sh[32*DA_PITCH];
    __shared__ float2 Wi[2*16*128];

    int tid  = threadIdx.x;
    int row0 = blockIdx.x * 32;
    int tx = tid & 31, ty = tid >> 5;
    int c0 = tx * 4;
    int r0 = ty * 4;

    float2 dacc[2][4][4];
    #pragma unroll
    for (int m = 0; m < 2; m++)
        #pragma unroll
        for (int r = 0; r < 4; r++)
            #pragma unroll
            for (int cc = 0; cc < 4; cc++) dacc[m][r][cc] = make_float2(0.f, 0.f);

    for (int k0 = 0; k0 < 128; k0 += 32) {
        __syncthreads();
        #pragma unroll
        for (int i = 0; i < 4; i++) {
            int r = ty + 8*i;
            A_sh[r*DA_PITCH + tx] = A[(size_t)(row0 + r) * 128 + k0 + tx];
        }
        #pragma unroll
        for (int i = 0; i < 16; i++) {
            int idx = tid + 256*i;
            int m = idx >> 11, kp = (idx >> 7) & 15, cc = idx & 127;
            const float* W = m ? Wb : Wa;
            Wi[idx] = make_float2(W[(size_t)(k0 + 2*kp) * 128 + cc],
                                  W[(size_t)(k0 + 2*kp + 1) * 128 + cc]);
        }
        __syncthreads();

        #pragma unroll 4
        for (int kp = 0; kp < 16; kp++) {
            float2 ar[4];
            #pragma unroll
            for (int r = 0; r < 4; r++)
                ar[r] = *(const float2*)(A_sh + (r0 + r)*DA_PITCH + 2*kp);

            float2 uwa[4], uwb[4];
            {
                const float4* wa4 = (const float4*)(Wi + kp*128 + c0);
                const float4* wb4 = (const float4*)(Wi + 2048 + kp*128 + c0);
                float4 waA = wa4[0];
                float4 waB = wa4[1];
                float4 wbA = wb4[0];
                float4 wbB = wb4[1];
                uwa[0] = make_float2(waA.x, waA.y);
                uwa[1] = make_float2(waA.z, waA.w);
                uwa[2] = make_float2(waB.x, waB.y);
                uwa[3] = make_float2(waB.z, waB.w);
                uwb[0] = make_float2(wbA.x, wbA.y);
                uwb[1] = make_float2(wbA.z, wbA.w);
                uwb[2] = make_float2(wbB.x, wbB.y);
                uwb[3] = make_float2(wbB.z, wbB.w);
            }

            #pragma unroll
            for (int r = 0; r < 4; r++) {
                #pragma unroll
                for (int cc = 0; cc < 4; cc++) {
                    dacc[0][r][cc] = pfma2(ar[r], uwa[cc], dacc[0][r][cc]);
                    dacc[1][r][cc] = pfma2(ar[r], uwb[cc], dacc[1][r][cc]);
                }
            }
        }
    }

    float bb[4];
    #pragma unroll
    for (int cc = 0; cc < 4; cc++) bb[cc] = biasB[c0 + cc];
    #pragma unroll
    for (int r = 0; r < 4; r++) {
        int row = row0 + r0 + r;
        float4 oa, ob;
        oa.x = dacc[0][r][0].x + dacc[0][r][0].y;
        oa.y = dacc[0][r][1].x + dacc[0][r][1].y;
        oa.z = dacc[0][r][2].x + dacc[0][r][2].y;
        oa.w = dacc[0][r][3].x + dacc[0][r][3].y;
        ob.x = dacc[1][r][0].x + dacc[1][r][0].y + bb[0];
        ob.y = dacc[1][r][1].x + dacc[1][r][1].y + bb[1];
        ob.z = dacc[1][r][2].x + dacc[1][r][2].y + bb[2];
        ob.w = dacc[1][r][3].x + dacc[1][r][3].y + bb[3];
        *(float4*)&Ca[(size_t)row*128 + c0] = oa;
        *(float4*)&Cb[(size_t)row*128 + c0] = ob;
    }
}

// ---------------- proven GEMM (qsW) + qstatus bf16 convert fold-in ----------------
__global__ __launch_bounds__(256) void gemm128_kernel(
    const float* __restrict__ A, const float* __restrict__ Wm,
    const float* __restrict__ bias, float* __restrict__ C,
    const float* __restrict__ qstatus)
{
    __shared__ float A_sh[32*33];
    __shared__ float W_sh[32*128];
    int tid  = threadIdx.x;
    int row0 = blockIdx.x * 32;
    int tx = tid & 31, ty = tid >> 5;
    int r0 = ty * 4, c0 = tx * 4;

    for (int i = blockIdx.x * 256 + tid; i < Bc*128*128; i += 256*256) {
        float v = qstatus[i];
        __nv_bfloat16 vhi = __float2bfloat16(v);
        __nv_bfloat16 vlo = __float2bfloat16(v - __bfloat162float(vhi));
        g_QShi[i] = vhi;
        g_QSlo[i] = vlo;
    }

    float2 gacc[4][2];
    #pragma unroll
    for (int r = 0; r < 4; r++) {
        gacc[r][0] = make_float2(0.f, 0.f);
        gacc[r][1] = make_float2(0.f, 0.f);
    }

    for (int k0 = 0; k0 < 128; k0 += 32) {
        __syncthreads();
        #pragma unroll
        for (int rr = 0; rr < 32; rr += 8) {
            int r = rr + ty;
            A_sh[tx*33 + r] = A[(size_t)(row0 + r) * 128 + k0 + tx];
        }
        for (int i = tid; i < 32*128; i += 256)
            W_sh[i] = Wm[(size_t)(k0 + (i >> 7)) * 128 + (i & 127)];
        __syncthreads();
        #pragma unroll
        for (int k = 0; k < 32; k++) {
            float4 w = *(const float4*)&W_sh[k*128 + c0];
            float2 wl = make_float2(w.x, w.y);
            float2 wh = make_float2(w.z, w.w);
            #pragma unroll
            for (int rr = 0; rr < 4; rr++) {
                float a = A_sh[k*33 + r0 + rr];
                float2 aa = make_float2(a, a);
                gacc[rr][0] = pfma2(aa, wl, gacc[rr][0]);
                gacc[rr][1] = pfma2(aa, wh, gacc[rr][1]);
            }
        }
    }
    float bb0 = bias ? bias[c0+0] : 0.f;
    float bb1 = bias ? bias[c0+1] : 0.f;
    float bb2 = bias ? bias[c0+2] : 0.f;
    float bb3 = bias ? bias[c0+3] : 0.f;
    #pragma unroll
    for (int rr = 0; rr < 4; rr++) {
        float4 o;
        o.x = gacc[rr][0].x + bb0; o.y = gacc[rr][0].y + bb1;
        o.z = gacc[rr][1].x + bb2; o.w = gacc[rr][1].y + bb3;
        *(float4*)&C[(size_t)(row0 + r0 + rr) * 128 + c0] = o;
    }
}

// ---------------- fused kernel: 1024 threads, all B via smem LDSM (R12 layout) ----------------
#define PITCHB 272
#define W2T_HI 0
#define W2T_LO 34816
#define H1_HI  69632
#define H1_LO  113152
#define QS_HI  69632
#define QS_LO  113152
#define QWB_HI 156672
#define QWB_LO 165376
#define CO_B   174080
#define P2_B   190464
#define BW_B   200704
#define F_BYTES 201728

__global__ __launch_bounds__(1024, 1) void fused_kernel(
    const float* __restrict__ qw, const float* __restrict__ q1,
    const float* __restrict__ qsw,
    const float* __restrict__ b2, const float* __restrict__ W3,
    const float* __restrict__ b3, float* __restrict__ logits)
{
    extern __shared__ float sm[];
    unsigned base_u = smem_u32_of(sm);
    char* basep = (char*)sm;

    float* p2_sh = (float*)(basep + P2_B);
    float* bw_sh = (float*)(basep + BW_B);
    float* co_sh = (float*)(basep + CO_B);   // 32 x 128 fp32

    int bw = blockIdx.x;
    int b  = bw >> 4;
    int tid = threadIdx.x;

    // ---- stage loads: W2T, QS images (re-pitched), qw->bf16, b2|W3 ----
    {
        const float4* s1 = (const float4*)g_W2Thi;
        const float4* s2 = (const float4*)g_W2Tlo;
        const float4* s3 = (const float4*)(g_QShi + (size_t)b * 16384);
        const float4* s4 = (const float4*)(g_QSlo + (size_t)b * 16384);
        for (int i = tid; i < 2048; i += 1024) {
            int f = i >> 4, k4 = i & 15;
            *(float4*)(basep + W2T_HI + f*PITCHB + k4*16) = s1[i];
            *(float4*)(basep + W2T_LO + f*PITCHB + k4*16) = s2[i];
            *(float4*)(basep + QS_HI  + f*PITCHB + k4*16) = s3[i];
            *(float4*)(basep + QS_LO  + f*PITCHB + k4*16) = s4[i];
        }
    }
    {
        const float* qwb = qw + (size_t)bw * 2560;
        for (int i = tid; i < 2048; i += 1024) {
            int row = i >> 6, kp = i & 63;
            __nv_bfloat162 hp, lp;
            if (row < Sc) {
                float2 v = *(const float2*)(qwb + row * 128 + 2*kp);
                __nv_bfloat16 hx = __float2bfloat16(v.x);
                __nv_bfloat16 hy = __float2bfloat16(v.y);
                hp.x = hx; hp.y = hy;
                lp.x = __float2bfloat16(v.x - __bfloat162float(hx));
                lp.y = __float2bfloat16(v.y - __bfloat162float(hy));
            } else {
                hp.x = __float2bfloat16(0.f); hp.y = hp.x;
                lp.x = hp.x; lp.y = hp.x;
            }
            *(unsigned*)(basep + QWB_HI + row*PITCHB + kp*4) = *(unsigned*)&hp;
            *(unsigned*)(basep + QWB_LO + row*PITCHB + kp*4) = *(unsigned*)&lp;
        }
    }
    if (tid < 128) bw_sh[tid] = b2[tid];
    else if (tid < 256) bw_sh[tid] = W3[tid - 128];
    __syncthreads();

    // ---- co[20x128] = qw @ qstatus^T ; 32 warps = 2mt x 16np, smem LDSM B ----
    {
        int lane = tid & 31;
        int wrp  = tid >> 5;
        int mt   = wrp >> 4;                 // 0..1
        int np   = wrp & 15;                 // r-cols 8np..8np+7

        unsigned a_hi = base_u + (unsigned)(QWB_HI + (lane & 15) * PITCHB
                      + (lane >> 4) * 16 + mt * 16 * PITCHB);
        unsigned a_lo = a_hi + (unsigned)(QWB_LO - QWB_HI);
        unsigned baddr = base_u + (unsigned)(QS_HI
                       + (8*np + (lane & 7)) * PITCHB + ((lane >> 3) & 1) * 16);
        unsigned baddr_lo = baddr + (unsigned)(QS_LO - QS_HI);

        float d[4] = {0.f, 0.f, 0.f, 0.f};
        #pragma unroll
        for (int ks = 0; ks < 8; ks++) {
            unsigned ah[4], al[4], bh[2], bl[2];
            ldsm_x4(ah, a_hi + ks*32);
            ldsm_x4(al, a_lo + ks*32);
            ldsm_x2(bh, baddr + ks*32);
            ldsm_x2(bl, baddr_lo + ks*32);
            mma16816(d, ah, bh);
            mma16816(d, ah, bl);
            mma16816(d, al, bh);
            mma16816(d, al, bl);
        }
        int r0 = mt * 16 + (lane >> 2);
        int c0 = 8*np + 2*(lane & 3);
        co_sh[r0 * 128 + c0]           = d[0];
        co_sh[r0 * 128 + c0 + 1]       = d[1];
        co_sh[(r0 + 8) * 128 + c0]     = d[2];
        co_sh[(r0 + 8) * 128 + c0 + 1] = d[3];
    }
    __syncthreads();

    // ---- masked softmax over x per (s,n); p2 as [n][s][x] ----
    if (tid < Sc * Nc) {
        int s = tid >> 3, n = tid & 7;
        float vals[16];
        float m = -3.4e38f;
        #pragma unroll
        for (int x = 0; x < 16; x++) {
            float v = co_sh[s * 128 + x * 8 + n];
            if (v == 0.f) v = -INF_;
            vals[x] = v;
            m = fmaxf(m, v);
        }
        float sum = 0.f;
        #pragma unroll
        for (int x = 0; x < 16; x++) { float e = expf(vals[x] - m); vals[x] = e; sum += e; }
        float rs = 1.f / sum;
        #pragma unroll
        for (int x = 0; x < 16; x++)
            p2_sh[n * 320 + s * 16 + x] = vals[x] * rs;
    }
    __syncthreads();   // QS fully consumed; h1 region free

    // ---- layer1 -> bf16 hi/lo h1 images; 1024 threads: (n, s-half, u2) ----
    {
        int n  = tid >> 7;
        int sh = (tid >> 6) & 1;
        int u2 = tid & 63;
        const float* qswb = qsw + ((size_t)b * Wc * Nc + n) * Uc + 2 * u2;
        float2 qv[16];
        #pragma unroll
        for (int x = 0; x < 16; x++)
            qv[x] = *(const float2*)(qswb + (size_t)x * Nc * Uc);

        const float* q1b = q1 + (size_t)bw * 2560;
        const float4* pp_base = (const float4*)(p2_sh + n * 320);
        char* hhi = basep + H1_HI;
        char* hlo = basep + H1_LO;

        #pragma unroll
        for (int si = 0; si < 10; si++) {
            int s = sh * 10 + si;
            float4 p0 = pp_base[s*4 + 0];
            float4 p1 = pp_base[s*4 + 1];
            float4 p2v = pp_base[s*4 + 2];
            float4 p3 = pp_base[s*4 + 3];
            float2 a = make_float2(0.f, 0.f);
            a = pfma2(make_float2(p0.x, p0.x), qv[0],  a);
            a = pfma2(make_float2(p0.y, p0.y), qv[1],  a);
            a = pfma2(make_float2(p0.z, p0.z), qv[2],  a);
            a = pfma2(make_float2(p0.w, p0.w), qv[3],  a);
            a = pfma2(make_float2(p1.x, p1.x), qv[4],  a);
            a = pfma2(make_float2(p1.y, p1.y), qv[5],  a);
            a = pfma2(make_float2(p1.z, p1.z), qv[6],  a);
            a = pfma2(make_float2(p1.w, p1.w), qv[7],  a);
            a = pfma2(make_float2(p2v.x, p2v.x), qv[8],  a);
            a = pfma2(make_float2(p2v.y, p2v.y), qv[9],  a);
            a = pfma2(make_float2(p2v.z, p2v.z), qv[10], a);
            a = pfma2(make_float2(p2v.w, p2v.w), qv[11], a);
            a = pfma2(make_float2(p3.x, p3.x), qv[12], a);
            a = pfma2(make_float2(p3.y, p3.y), qv[13], a);
            a = pfma2(make_float2(p3.z, p3.z), qv[14], a);
            a = pfma2(make_float2(p3.w, p3.w), qv[15], a);

            float2 base = *(const float2*)(q1b + s * 128 + 2 * u2);
            float hx = fmaxf(a.x + base.x, 0.f);
            float hy = fmaxf(a.y + base.y, 0.f);

            __nv_bfloat16 bhx = __float2bfloat16(hx);
            __nv_bfloat16 bhy = __float2bfloat16(hy);
            __nv_bfloat16 blx = __float2bfloat16(hx - __bfloat162float(bhx));
            __nv_bfloat16 bly = __float2bfloat16(hy - __bfloat162float(bhy));
            __nv_bfloat162 hp;
            hp.x = bhx; hp.y = bhy;
            __nv_bfloat162 lp;
            lp.x = blx; lp.y = bly;

            int row = s * 8 + n;
            *(unsigned*)(hhi + row*PITCHB + u2*4) = *(unsigned*)&hp;
            *(unsigned*)(hlo + row*PITCHB + u2*4) = *(unsigned*)&lp;
        }
    }
    __syncthreads();

    // ---- layer2: 32 warps = 4 m-groups {3,3,2,2} x 8 n-pairs; smem LDSM B ----
    {
        int lane = tid & 31;
        int wrp  = tid >> 5;
        int g    = wrp >> 3;
        int p    = wrp & 7;
        int mcnt = (g < 2) ? 3 : 2;
        int mst  = (g < 2) ? 3*g : 6 + 2*(g - 2);

        unsigned bbase[2];
        #pragma unroll
        for (int nt = 0; nt < 2; nt++)
            bbase[nt] = base_u + (unsigned)(W2T_HI
                      + (16*p + 8*nt + (lane & 7)) * PITCHB
                      + ((lane >> 3) & 1) * 16);

        unsigned abase_hi = base_u + (unsigned)(H1_HI + (lane & 15) * PITCHB + (lane >> 4) * 16);
        unsigned abase_lo = abase_hi + (unsigned)(H1_LO - H1_HI);
        float* part_sh = p2_sh;

        float b2c[2][2], w3c[2][2];
        #pragma unroll
        for (int nt = 0; nt < 2; nt++) {
            int c0 = 16*p + 8*nt + 2*(lane & 3);
            b2c[nt][0] = bw_sh[c0];       b2c[nt][1] = bw_sh[c0+1];
            w3c[nt][0] = bw_sh[128+c0];   w3c[nt][1] = bw_sh[128+c0+1];
        }
        float b3v = b3[0];
        (void)b3v;

        #pragma unroll
        for (int mi = 0; mi < 3; mi++) {
            if (mi < mcnt) {
                int mt = mst + mi;
                float d[2][4];
                #pragma unroll
                for (int nt = 0; nt < 2; nt++)
                    #pragma unroll
                    for (int j = 0; j < 4; j++) d[nt][j] = 0.f;

                unsigned am = abase_hi + (unsigned)(mt * 16 * PITCHB);
                unsigned al = abase_lo + (unsigned)(mt * 16 * PITCHB);
                #pragma unroll
                for (int ks = 0; ks < 8; ks++) {
                    unsigned ah[4], alr[4];
                    ldsm_x4(ah,  am + ks*32);
                    ldsm_x4(alr, al + ks*32);
                    #pragma unroll
                    for (int nt = 0; nt < 2; nt++) {
                        unsigned bh[2], bl[2];
                        ldsm_x2(bh, bbase[nt] + ks*32);
                        ldsm_x2(bl, bbase[nt] + (unsigned)(W2T_LO - W2T_HI) + ks*32);
                        mma16816(d[nt], ah,  bh);
                        mma16816(d[nt], ah,  bl);
                        mma16816(d[nt], alr, bh);
                    }
                }
                float v0 = 0.f, v1 = 0.f;
                #pragma unroll
                for (int nt = 0; nt < 2; nt++) {
                    v0 += fmaxf(d[nt][0] + b2c[nt][0], 0.f) * w3c[nt][0]
                        + fmaxf(d[nt][1] + b2c[nt][1], 0.f) * w3c[nt][1];
                    v1 += fmaxf(d[nt][2] + b2c[nt][0], 0.f) * w3c[nt][0]
                        + fmaxf(d[nt][3] + b2c[nt][1], 0.f) * w3c[nt][1];
                }
                v0 += __shfl_xor_sync(0xffffffffu, v0, 1);
                v0 += __shfl_xor_sync(0xffffffffu, v0, 2);
                v1 += __shfl_xor_sync(0xffffffffu, v1, 1);
                v1 += __shfl_xor_sync(0xffffffffu, v1, 2);
                if ((lane & 3) == 0) {
                    int r0 = mt * 16 + (lane >> 2);
                    part_sh[r0 * 8 + p]       = v0;
                    part_sh[(r0 + 8) * 8 + p] = v1;
                }
            }
        }
    }
    __syncthreads();

    if (tid < 160) {
        const float4* pr = (const float4*)(p2_sh + tid * 8);
        float4 u = pr[0], v = pr[1];
        logits[(size_t)bw * 160 + tid] =
            u.x + u.y + u.z + u.w + v.x + v.y + v.z + v.w + b3[0];
    }
}

// ---------------- finalize ----------------
__global__ __launch_bounds__(160) void finalize_kernel(
    const float* __restrict__ logits, const float* __restrict__ mask,
    float* __restrict__ out, int scalar_idx, int logits_off)
{
    int b = blockIdx.x;
    int k = threadIdx.x;
    float m = -3.4e38f;
    #pragma unroll
    for (int w = 0; w < Wc; w++) {
        size_t idx = (size_t)(b*Wc + w) * (Sc*Nc) + k;
        float v = logits[idx] + mask[idx];
        m = fmaxf(m, v);
    }
    out[b*(Sc*Nc) + k] = (m > 0.f) ? 1.f : 0.f;
    out[(size_t)logits_off + b*(Sc*Nc) + k] = m;
    if (b == 0 && k == 0 && scalar_idx >= 0) out[scalar_idx] = 160.0f;
}

// ---------------- host launcher ----------------
extern "C" void kernel_launch(void* const* d_in, const int* in_sizes, int n_in,
                              void* d_out, int out_size)
{
    const float* h    = (const float*)d_in[0];
    const float* c    = (const float*)d_in[1];
    const float* pos  = (const float*)d_in[3];
    const float* qst  = (const float*)d_in[4];
    const float* mask = (const float*)d_in[5];
    const float* wgt  = (const float*)d_in[6];
    const float* W1   = (const float*)d_in[7];
    const float* b1   = (const float*)d_in[8];
    const float* W2   = (const float*)d_in[9];
    const float* b2   = (const float*)d_in[10];
    const float* W3   = (const float*)d_in[11];
    const float* b3   = (const float*)d_in[12];
    float* out = (float*)d_out;

    float *qslot_p, *qw_p, *qslotw1_p, *qsw_p, *logits_p;
    cudaGetSymbolAddress((void**)&qslot_p,   g_qslot);
    cudaGetSymbolAddress((void**)&qw_p,      g_qw);
    cudaGetSymbolAddress((void**)&qslotw1_p, g_qslotW1);
    cudaGetSymbolAddress((void**)&qsw_p,     g_qsW);
    cudaGetSymbolAddress((void**)&logits_p,  g_logits);

    const int M_qs = Bc*Wc*Sc;   // 20480
    const int M_st = Bc*Wc*Nc;   // 8192

    cudaFuncSetAttribute(qslot_kernel,
        cudaFuncAttributeMaxDynamicSharedMemorySize, Q_SMEM);
    cudaFuncSetAttribute(fused_kernel,
        cudaFuncAttributeMaxDynamicSharedMemorySize, F_BYTES);

    gemm128_kernel<<<M_st/32, 256>>>(qst, W1 + 128*128, nullptr, qsw_p, qst);  // 1 (+ QS bf16 prep)
    qslot_kernel<<<Bc*Wc, 256, Q_SMEM>>>(h, c, pos, qslot_p, W2);              // 2 (+ W2^T bf16 prep)
    gemm_dual_kernel<<<M_qs/32, 256>>>(qslot_p, wgt, W1, b1, qw_p, qslotw1_p); // 3
    fused_kernel<<<Bc*Wc, 1024, F_BYTES>>>(                                    // 4  <-- profiled
        qw_p, qslotw1_p, qsw_p, b2, W3, b3, logits_p);

    int scalar_idx = (out_size == 2*Bc*Sc*Nc + 1) ? Bc*Sc*Nc : -1;
    int logits_off = out_size - Bc*Sc*Nc;
    finalize_kernel<<<Bc, 160>>>(logits_p, mask, out, scalar_idx, logits_off); // 5
}

// round 15
// speedup vs baseline: 1.2758x; 1.0001x over previous
#include <cuda_runtime.h>
#include <cuda_bf16.h>
#include <cstdint>
#include <math.h>

#define Bc 64
#define Wc 16
#define Tc 64
#define Uc 128
#define Sc 20
#define Nc 8
#define INF_ 100000.0f

// ---------------- scratch ----------------
__device__ float g_qslot[Bc*Wc*Sc*Uc];
__device__ float g_qw[Bc*Wc*Sc*Uc];
__device__ float g_qslotW1[Bc*Wc*Sc*Uc];
__device__ float g_qsW[Bc*Wc*Nc*Uc];
__device__ float g_logits[Bc*Wc*Sc*Nc];
__device__ __align__(16) __nv_bfloat16 g_W2Thi[16384];
__device__ __align__(16) __nv_bfloat16 g_W2Tlo[16384];
__device__ __align__(16) __nv_bfloat16 g_QShi[Bc*128*128];
__device__ __align__(16) __nv_bfloat16 g_QSlo[Bc*128*128];

__device__ __forceinline__ float2 pfma2(float2 a, float2 b, float2 c) {
    unsigned long long ua = *reinterpret_cast<unsigned long long*>(&a);
    unsigned long long ub = *reinterpret_cast<unsigned long long*>(&b);
    unsigned long long uc = *reinterpret_cast<unsigned long long*>(&c);
    unsigned long long ud;
    asm("fma.rn.f32x2 %0, %1, %2, %3;" : "=l"(ud) : "l"(ua), "l"(ub), "l"(uc));
    return *reinterpret_cast<float2*>(&ud);
}

__device__ __forceinline__ unsigned smem_u32_of(const void* p) {
    unsigned a;
    asm("{ .reg .u64 t; cvta.to.shared.u64 t, %1; cvt.u32.u64 %0, t; }" : "=r"(a) : "l"(p));
    return a;
}

__device__ __forceinline__ void mma16816(float* d, const unsigned* a, const unsigned* b) {
    asm volatile(
        "mma.sync.aligned.m16n8k16.row.col.f32.bf16.bf16.f32 "
        "{%0,%1,%2,%3}, {%4,%5,%6,%7}, {%8,%9}, {%0,%1,%2,%3};"
        : "+f"(d[0]), "+f"(d[1]), "+f"(d[2]), "+f"(d[3])
        : "r"(a[0]), "r"(a[1]), "r"(a[2]), "r"(a[3]), "r"(b[0]), "r"(b[1]));
}

__device__ __forceinline__ void ldsm_x4(unsigned* r, unsigned addr) {
    asm volatile("ldmatrix.sync.aligned.m8n8.x4.shared.b16 {%0,%1,%2,%3}, [%4];"
        : "=r"(r[0]), "=r"(r[1]), "=r"(r[2]), "=r"(r[3]) : "r"(addr));
}
__device__ __forceinline__ void ldsm_x2(unsigned* r, unsigned addr) {
    asm volatile("ldmatrix.sync.aligned.m8n8.x2.shared.b16 {%0,%1}, [%2];"
        : "=r"(r[0]), "=r"(r[1]) : "r"(addr));
}

// ---------------- kernel 1: utterance attention -> q_slot + W2^T bf16 prep fold-in ----------------
#define QP 132
#define Q_SMEM ((Tc*QP + Sc*QP + Sc*Tc) * 4)
__global__ __launch_bounds__(256) void qslot_kernel(
    const float* __restrict__ h, const float* __restrict__ c,
    const float* __restrict__ pos, float* __restrict__ qslot,
    const float* __restrict__ W2)
{
    extern __shared__ float qs[];
    float* h_sh = qs;
    float* c_sh = qs + Tc*QP;
    float* p_sh = qs + Tc*QP + Sc*QP;

    int bw  = blockIdx.x;
    int tid = threadIdx.x;

    if (bw < 64) {
        int idx = bw * 256 + tid;
        int f = idx >> 7, k = idx & 127;
        float val = W2[(size_t)k * 128 + f];
        __nv_bfloat16 vhi = __float2bfloat16(val);
        __nv_bfloat16 vlo = __float2bfloat16(val - __bfloat162float(vhi));
        g_W2Thi[idx] = vhi;
        g_W2Tlo[idx] = vlo;
    }

    const float4* hb = (const float4*)(h + (size_t)bw * Tc * Uc);
    for (int i = tid; i < Tc*32; i += 256) {
        int r = i >> 5, c4 = i & 31;
        *(float4*)(h_sh + r*QP + 4*c4) = hb[i];
    }
    const float4* cg = (const float4*)c;
    for (int i = tid; i < Sc*32; i += 256) {
        int r = i >> 5, c4 = i & 31;
        *(float4*)(c_sh + r*QP + 4*c4) = cg[i];
    }
    __syncthreads();

    for (int task = tid; task < 320; task += 256) {
        int t = task & 63, sg = task >> 6;
        const float4* hr = (const float4*)(h_sh + t*QP);
        float2 pa[4];
        #pragma unroll
        for (int i = 0; i < 4; i++) pa[i] = make_float2(0.f, 0.f);
        #pragma unroll 8
        for (int u4 = 0; u4 < 32; u4++) {
            float4 hv = hr[u4];
            float2 hl = make_float2(hv.x, hv.y);
            float2 hh = make_float2(hv.z, hv.w);
            #pragma unroll
            for (int i = 0; i < 4; i++) {
                float4 cv = *(const float4*)(c_sh + (4*sg+i)*QP + 4*u4);
                pa[i] = pfma2(make_float2(cv.x, cv.y), hl, pa[i]);
                pa[i] = pfma2(make_float2(cv.z, cv.w), hh, pa[i]);
            }
        }
        #pragma unroll
        for (int i = 0; i < 4; i++)
            p_sh[(4*sg+i)*Tc + t] = pa[i].x + pa[i].y;
    }
    __syncthreads();

    if (tid < Sc) {
        float* pr = p_sh + tid * Tc;
        float m = -3.4e38f;
        #pragma unroll
        for (int t = 0; t < Tc; t++) {
            float v = pr[t];
            if (v == 0.f) v = -INF_;
            pr[t] = v;
            m = fmaxf(m, v);
        }
        float sum = 0.f;
        #pragma unroll
        for (int t = 0; t < Tc; t++) { float e = expf(pr[t] - m); pr[t] = e; sum += e; }
        float r = 1.f / sum;
        #pragma unroll
        for (int t = 0; t < Tc; t++) pr[t] *= r;
    }
    __syncthreads();

    if (tid < 160) {
        int u4 = tid & 31, sg = tid >> 5;
        float2 aL[4], aH[4];
        #pragma unroll
        for (int i = 0; i < 4; i++) { aL[i] = make_float2(0.f, 0.f); aH[i] = make_float2(0.f, 0.f); }
        #pragma unroll 4
        for (int t = 0; t < Tc; t++) {
            float4 hv = *(const float4*)(h_sh + t*QP + 4*u4);
            float2 hl = make_float2(hv.x, hv.y);
            float2 hh = make_float2(hv.z, hv.w);
            #pragma unroll
            for (int i = 0; i < 4; i++) {
                float p = p_sh[(4*sg+i)*Tc + t];
                float2 pp = make_float2(p, p);
                aL[i] = pfma2(pp, hl, aL[i]);
                aH[i] = pfma2(pp, hh, aH[i]);
            }
        }
        const float* posb = pos + (size_t)bw * Sc * Uc;
        float* qb = qslot + (size_t)bw * Sc * Uc;
        #pragma unroll
        for (int i = 0; i < 4; i++) {
            int s = 4*sg + i;
            float4 pv = *(const float4*)(posb + s*128 + 4*u4);
            float4 o;
            o.x = aL[i].x + pv.x; o.y = aL[i].y + pv.y;
            o.z = aH[i].x + pv.z; o.w = aH[i].y + pv.w;
            *(float4*)(qb + s*128 + 4*u4) = o;
        }
    }
}

// ---------------- dual-output GEMM (proven) ----------------
#define DA_PITCH 34
__global__ __launch_bounds__(256) void gemm_dual_kernel(
    const float* __restrict__ A,
    const float* __restrict__ Wa, const float* __restrict__ Wb,
    const float* __restrict__ biasB,
    float* __restrict__ Ca, float* __restrict__ Cb)
{
    __shared__ float  A_sh[32*DA_PITCH];
    __shared__ float2 Wi[2*16*128];

    int tid  = threadIdx.x;
    int row0 = blockIdx.x * 32;
    int tx = tid & 31, ty = tid >> 5;
    int c0 = tx * 4;
    int r0 = ty * 4;

    float2 dacc[2][4][4];
    #pragma unroll
    for (int m = 0; m < 2; m++)
        #pragma unroll
        for (int r = 0; r < 4; r++)
            #pragma unroll
            for (int cc = 0; cc < 4; cc++) dacc[m][r][cc] = make_float2(0.f, 0.f);

    for (int k0 = 0; k0 < 128; k0 += 32) {
        __syncthreads();
        #pragma unroll
        for (int i = 0; i < 4; i++) {
            int r = ty + 8*i;
            A_sh[r*DA_PITCH + tx] = A[(size_t)(row0 + r) * 128 + k0 + tx];
        }
        #pragma unroll
        for (int i = 0; i < 16; i++) {
            int idx = tid + 256*i;
            int m = idx >> 11, kp = (idx >> 7) & 15, cc = idx & 127;
            const float* W = m ? Wb : Wa;
            Wi[idx] = make_float2(W[(size_t)(k0 + 2*kp) * 128 + cc],
                                  W[(size_t)(k0 + 2*kp + 1) * 128 + cc]);
        }
        __syncthreads();

        #pragma unroll 4
        for (int kp = 0; kp < 16; kp++) {
            float2 ar[4];
            #pragma unroll
            for (int r = 0; r < 4; r++)
                ar[r] = *(const float2*)(A_sh + (r0 + r)*DA_PITCH + 2*kp);

            float2 uwa[4], uwb[4];
            {
                const float4* wa4 = (const float4*)(Wi + kp*128 + c0);
                const float4* wb4 = (const float4*)(Wi + 2048 + kp*128 + c0);
                float4 waA = wa4[0];
                float4 waB = wa4[1];
                float4 wbA = wb4[0];
                float4 wbB = wb4[1];
                uwa[0] = make_float2(waA.x, waA.y);
                uwa[1] = make_float2(waA.z, waA.w);
                uwa[2] = make_float2(waB.x, waB.y);
                uwa[3] = make_float2(waB.z, waB.w);
                uwb[0] = make_float2(wbA.x, wbA.y);
                uwb[1] = make_float2(wbA.z, wbA.w);
                uwb[2] = make_float2(wbB.x, wbB.y);
                uwb[3] = make_float2(wbB.z, wbB.w);
            }

            #pragma unroll
            for (int r = 0; r < 4; r++) {
                #pragma unroll
                for (int cc = 0; cc < 4; cc++) {
                    dacc[0][r][cc] = pfma2(ar[r], uwa[cc], dacc[0][r][cc]);
                    dacc[1][r][cc] = pfma2(ar[r], uwb[cc], dacc[1][r][cc]);
                }
            }
        }
    }

    float bb[4];
    #pragma unroll
    for (int cc = 0; cc < 4; cc++) bb[cc] = biasB[c0 + cc];
    #pragma unroll
    for (int r = 0; r < 4; r++) {
        int row = row0 + r0 + r;
        float4 oa, ob;
        oa.x = dacc[0][r][0].x + dacc[0][r][0].y;
        oa.y = dacc[0][r][1].x + dacc[0][r][1].y;
        oa.z = dacc[0][r][2].x + dacc[0][r][2].y;
        oa.w = dacc[0][r][3].x + dacc[0][r][3].y;
        ob.x = dacc[1][r][0].x + dacc[1][r][0].y + bb[0];
        ob.y = dacc[1][r][1].x + dacc[1][r][1].y + bb[1];
        ob.z = dacc[1][r][2].x + dacc[1][r][2].y + bb[2];
        ob.w = dacc[1][r][3].x + dacc[1][r][3].y + bb[3];
        *(float4*)&Ca[(size_t)row*128 + c0] = oa;
        *(float4*)&Cb[(size_t)row*128 + c0] = ob;
    }
}

// ---------------- proven GEMM (qsW) + qstatus bf16 convert fold-in ----------------
__global__ __launch_bounds__(256) void gemm128_kernel(
    const float* __restrict__ A, const float* __restrict__ Wm,
    const float* __restrict__ bias, float* __restrict__ C,
    const float* __restrict__ qstatus)
{
    __shared__ float A_sh[32*33];
    __shared__ float W_sh[32*128];
    int tid  = threadIdx.x;
    int row0 = blockIdx.x * 32;
    int tx = tid & 31, ty = tid >> 5;
    int r0 = ty * 4, c0 = tx * 4;

    for (int i = blockIdx.x * 256 + tid; i < Bc*128*128; i += 256*256) {
        float v = qstatus[i];
        __nv_bfloat16 vhi = __float2bfloat16(v);
        __nv_bfloat16 vlo = __float2bfloat16(v - __bfloat162float(vhi));
        g_QShi[i] = vhi;
        g_QSlo[i] = vlo;
    }

    float2 gacc[4][2];
    #pragma unroll
    for (int r = 0; r < 4; r++) {
        gacc[r][0] = make_float2(0.f, 0.f);
        gacc[r][1] = make_float2(0.f, 0.f);
    }

    for (int k0 = 0; k0 < 128; k0 += 32) {
        __syncthreads();
        #pragma unroll
        for (int rr = 0; rr < 32; rr += 8) {
            int r = rr + ty;
            A_sh[tx*33 + r] = A[(size_t)(row0 + r) * 128 + k0 + tx];
        }
        for (int i = tid; i < 32*128; i += 256)
            W_sh[i] = Wm[(size_t)(k0 + (i >> 7)) * 128 + (i & 127)];
        __syncthreads();
        #pragma unroll
        for (int k = 0; k < 32; k++) {
            float4 w = *(const float4*)&W_sh[k*128 + c0];
            float2 wl = make_float2(w.x, w.y);
            float2 wh = make_float2(w.z, w.w);
            #pragma unroll
            for (int rr = 0; rr < 4; rr++) {
                float a = A_sh[k*33 + r0 + rr];
                float2 aa = make_float2(a, a);
                gacc[rr][0] = pfma2(aa, wl, gacc[rr][0]);
                gacc[rr][1] = pfma2(aa, wh, gacc[rr][1]);
            }
        }
    }
    float bb0 = bias ? bias[c0+0] : 0.f;
    float bb1 = bias ? bias[c0+1] : 0.f;
    float bb2 = bias ? bias[c0+2] : 0.f;
    float bb3 = bias ? bias[c0+3] : 0.f;
    #pragma unroll
    for (int rr = 0; rr < 4; rr++) {
        float4 o;
        o.x = gacc[rr][0].x + bb0; o.y = gacc[rr][0].y + bb1;
        o.z = gacc[rr][1].x + bb2; o.w = gacc[rr][1].y + bb3;
        *(float4*)&C[(size_t)(row0 + r0 + rr) * 128 + c0] = o;
    }
}

// ---------------- fused kernel: 1024 threads, smem LDSM, ks-outer layer2 ----------------
#define PITCHB 272
#define W2T_HI 0
#define W2T_LO 34816
#define H1_HI  69632
#define H1_LO  113152
#define QS_HI  69632
#define QS_LO  113152
#define QWB_HI 156672
#define QWB_LO 165376
#define CO_B   174080
#define P2_B   190464
#define BW_B   200704
#define F_BYTES 201728

__global__ __launch_bounds__(1024, 1) void fused_kernel(
    const float* __restrict__ qw, const float* __restrict__ q1,
    const float* __restrict__ qsw,
    const float* __restrict__ b2, const float* __restrict__ W3,
    const float* __restrict__ b3, float* __restrict__ logits)
{
    extern __shared__ float sm[];
    unsigned base_u = smem_u32_of(sm);
    char* basep = (char*)sm;

    float* p2_sh = (float*)(basep + P2_B);
    float* bw_sh = (float*)(basep + BW_B);
    float* co_sh = (float*)(basep + CO_B);

    int bw = blockIdx.x;
    int b  = bw >> 4;
    int tid = threadIdx.x;

    // ---- stage loads: W2T, QS images (re-pitched), qw->bf16, b2|W3 ----
    {
        const float4* s1 = (const float4*)g_W2Thi;
        const float4* s2 = (const float4*)g_W2Tlo;
        const float4* s3 = (const float4*)(g_QShi + (size_t)b * 16384);
        const float4* s4 = (const float4*)(g_QSlo + (size_t)b * 16384);
        for (int i = tid; i < 2048; i += 1024) {
            int f = i >> 4, k4 = i & 15;
            *(float4*)(basep + W2T_HI + f*PITCHB + k4*16) = s1[i];
            *(float4*)(basep + W2T_LO + f*PITCHB + k4*16) = s2[i];
            *(float4*)(basep + QS_HI  + f*PITCHB + k4*16) = s3[i];
            *(float4*)(basep + QS_LO  + f*PITCHB + k4*16) = s4[i];
        }
    }
    {
        const float* qwb = qw + (size_t)bw * 2560;
        for (int i = tid; i < 2048; i += 1024) {
            int row = i >> 6, kp = i & 63;
            __nv_bfloat162 hp, lp;
            if (row < Sc) {
                float2 v = *(const float2*)(qwb + row * 128 + 2*kp);
                __nv_bfloat16 hx = __float2bfloat16(v.x);
                __nv_bfloat16 hy = __float2bfloat16(v.y);
                hp.x = hx; hp.y = hy;
                lp.x = __float2bfloat16(v.x - __bfloat162float(hx));
                lp.y = __float2bfloat16(v.y - __bfloat162float(hy));
            } else {
                hp.x = __float2bfloat16(0.f); hp.y = hp.x;
                lp.x = hp.x; lp.y = hp.x;
            }
            *(unsigned*)(basep + QWB_HI + row*PITCHB + kp*4) = *(unsigned*)&hp;
            *(unsigned*)(basep + QWB_LO + row*PITCHB + kp*4) = *(unsigned*)&lp;
        }
    }
    if (tid < 128) bw_sh[tid] = b2[tid];
    else if (tid < 256) bw_sh[tid] = W3[tid - 128];
    __syncthreads();

    // ---- co[20x128] = qw @ qstatus^T ; 32 warps = 2mt x 16np, smem LDSM B ----
    {
        int lane = tid & 31;
        int wrp  = tid >> 5;
        int mt   = wrp >> 4;
        int np   = wrp & 15;

        unsigned a_hi = base_u + (unsigned)(QWB_HI + (lane & 15) * PITCHB
                      + (lane >> 4) * 16 + mt * 16 * PITCHB);
        unsigned a_lo = a_hi + (unsigned)(QWB_LO - QWB_HI);
        unsigned baddr = base_u + (unsigned)(QS_HI
                       + (8*np + (lane & 7)) * PITCHB + ((lane >> 3) & 1) * 16);
        unsigned baddr_lo = baddr + (unsigned)(QS_LO - QS_HI);

        float d[4] = {0.f, 0.f, 0.f, 0.f};
        #pragma unroll
        for (int ks = 0; ks < 8; ks++) {
            unsigned ah[4], al[4], bh[2], bl[2];
            ldsm_x4(ah, a_hi + ks*32);
            ldsm_x4(al, a_lo + ks*32);
            ldsm_x2(bh, baddr + ks*32);
            ldsm_x2(bl, baddr_lo + ks*32);
            mma16816(d, ah, bh);
            mma16816(d, ah, bl);
            mma16816(d, al, bh);
            mma16816(d, al, bl);
        }
        int r0 = mt * 16 + (lane >> 2);
        int c0 = 8*np + 2*(lane & 3);
        co_sh[r0 * 128 + c0]           = d[0];
        co_sh[r0 * 128 + c0 + 1]       = d[1];
        co_sh[(r0 + 8) * 128 + c0]     = d[2];
        co_sh[(r0 + 8) * 128 + c0 + 1] = d[3];
    }
    __syncthreads();

    // ---- masked softmax over x per (s,n); p2 as [n][s][x] ----
    if (tid < Sc * Nc) {
        int s = tid >> 3, n = tid & 7;
        float vals[16];
        float m = -3.4e38f;
        #pragma unroll
        for (int x = 0; x < 16; x++) {
            float v = co_sh[s * 128 + x * 8 + n];
            if (v == 0.f) v = -INF_;
            vals[x] = v;
            m = fmaxf(m, v);
        }
        float sum = 0.f;
        #pragma unroll
        for (int x = 0; x < 16; x++) { float e = expf(vals[x] - m); vals[x] = e; sum += e; }
        float rs = 1.f / sum;
        #pragma unroll
        for (int x = 0; x < 16; x++)
            p2_sh[n * 320 + s * 16 + x] = vals[x] * rs;
    }
    __syncthreads();

    // ---- layer1 -> bf16 hi/lo h1 images; (n, s-half, u2) ----
    {
        int n  = tid >> 7;
        int sh = (tid >> 6) & 1;
        int u2 = tid & 63;
        const float* qswb = qsw + ((size_t)b * Wc * Nc + n) * Uc + 2 * u2;
        float2 qv[16];
        #pragma unroll
        for (int x = 0; x < 16; x++)
            qv[x] = *(const float2*)(qswb + (size_t)x * Nc * Uc);

        const float* q1b = q1 + (size_t)bw * 2560;
        const float4* pp_base = (const float4*)(p2_sh + n * 320);
        char* hhi = basep + H1_HI;
        char* hlo = basep + H1_LO;

        #pragma unroll
        for (int si = 0; si < 10; si++) {
            int s = sh * 10 + si;
            float4 p0 = pp_base[s*4 + 0];
            float4 p1 = pp_base[s*4 + 1];
            float4 p2v = pp_base[s*4 + 2];
            float4 p3 = pp_base[s*4 + 3];
            float2 a = make_float2(0.f, 0.f);
            a = pfma2(make_float2(p0.x, p0.x), qv[0],  a);
            a = pfma2(make_float2(p0.y, p0.y), qv[1],  a);
            a = pfma2(make_float2(p0.z, p0.z), qv[2],  a);
            a = pfma2(make_float2(p0.w, p0.w), qv[3],  a);
            a = pfma2(make_float2(p1.x, p1.x), qv[4],  a);
            a = pfma2(make_float2(p1.y, p1.y), qv[5],  a);
            a = pfma2(make_float2(p1.z, p1.z), qv[6],  a);
            a = pfma2(make_float2(p1.w, p1.w), qv[7],  a);
            a = pfma2(make_float2(p2v.x, p2v.x), qv[8],  a);
            a = pfma2(make_float2(p2v.y, p2v.y), qv[9],  a);
            a = pfma2(make_float2(p2v.z, p2v.z), qv[10], a);
            a = pfma2(make_float2(p2v.w, p2v.w), qv[11], a);
            a = pfma2(make_float2(p3.x, p3.x), qv[12], a);
            a = pfma2(make_float2(p3.y, p3.y), qv[13], a);
            a = pfma2(make_float2(p3.z, p3.z), qv[14], a);
            a = pfma2(make_float2(p3.w, p3.w), qv[15], a);

            float2 base = *(const float2*)(q1b + s * 128 + 2 * u2);
            float hx = fmaxf(a.x + base.x, 0.f);
            float hy = fmaxf(a.y + base.y, 0.f);

            __nv_bfloat16 bhx = __float2bfloat16(hx);
            __nv_bfloat16 bhy = __float2bfloat16(hy);
            __nv_bfloat16 blx = __float2bfloat16(hx - __bfloat162float(bhx));
            __nv_bfloat16 bly = __float2bfloat16(hy - __bfloat162float(bhy));
            __nv_bfloat162 hp;
            hp.x = bhx; hp.y = bhy;
            __nv_bfloat162 lp;
            lp.x = blx; lp.y = bly;

            int row = s * 8 + n;
            *(unsigned*)(hhi + row*PITCHB + u2*4) = *(unsigned*)&hp;
            *(unsigned*)(hlo + row*PITCHB + u2*4) = *(unsigned*)&lp;
        }
    }
    __syncthreads();

    // ---- layer2: 32 warps = 4 m-groups {3,3,2,2} x 8 n-pairs; ks-outer, B reused across mi ----
    {
        int lane = tid & 31;
        int wrp  = tid >> 5;
        int g    = wrp >> 3;
        int p    = wrp & 7;
        int mcnt = (g < 2) ? 3 : 2;
        int mst  = (g < 2) ? 3*g : 6 + 2*(g - 2);

        unsigned bbase[2];
        #pragma unroll
        for (int nt = 0; nt < 2; nt++)
            bbase[nt] = base_u + (unsigned)(W2T_HI
                      + (16*p + 8*nt + (lane & 7)) * PITCHB
                      + ((lane >> 3) & 1) * 16);

        unsigned abase_hi = base_u + (unsigned)(H1_HI + (lane & 15) * PITCHB + (lane >> 4) * 16);
        unsigned abase_lo = abase_hi + (unsigned)(H1_LO - H1_HI);
        float* part_sh = p2_sh;

        float d[3][2][4];
        #pragma unroll
        for (int mi = 0; mi < 3; mi++)
            #pragma unroll
            for (int nt = 0; nt < 2; nt++)
                #pragma unroll
                for (int j = 0; j < 4; j++) d[mi][nt][j] = 0.f;

        #pragma unroll
        for (int ks = 0; ks < 8; ks++) {
            unsigned bh[2][2], bl[2][2];
            #pragma unroll
            for (int nt = 0; nt < 2; nt++) {
                ldsm_x2(bh[nt], bbase[nt] + ks*32);
                ldsm_x2(bl[nt], bbase[nt] + (unsigned)(W2T_LO - W2T_HI) + ks*32);
            }
            #pragma unroll
            for (int mi = 0; mi < 3; mi++) {
                if (mi < mcnt) {
                    int mt = mst + mi;
                    unsigned ah[4], alr[4];
                    ldsm_x4(ah,  abase_hi + (unsigned)(mt * 16 * PITCHB) + ks*32);
                    ldsm_x4(alr, abase_lo + (unsigned)(mt * 16 * PITCHB) + ks*32);
                    #pragma unroll
                    for (int nt = 0; nt < 2; nt++) {
                        mma16816(d[mi][nt], ah,  bh[nt]);
                        mma16816(d[mi][nt], ah,  bl[nt]);
                        mma16816(d[mi][nt], alr, bh[nt]);
                    }
                }
            }
        }

        float b2c[2][2], w3c[2][2];
        #pragma unroll
        for (int nt = 0; nt < 2; nt++) {
            int c0 = 16*p + 8*nt + 2*(lane & 3);
            b2c[nt][0] = bw_sh[c0];       b2c[nt][1] = bw_sh[c0+1];
            w3c[nt][0] = bw_sh[128+c0];   w3c[nt][1] = bw_sh[128+c0+1];
        }

        #pragma unroll
        for (int mi = 0; mi < 3; mi++) {
            if (mi < mcnt) {
                int mt = mst + mi;
                float v0 = 0.f, v1 = 0.f;
                #pragma unroll
                for (int nt = 0; nt < 2; nt++) {
                    v0 += fmaxf(d[mi][nt][0] + b2c[nt][0], 0.f) * w3c[nt][0]
                        + fmaxf(d[mi][nt][1] + b2c[nt][1], 0.f) * w3c[nt][1];
                    v1 += fmaxf(d[mi][nt][2] + b2c[nt][0], 0.f) * w3c[nt][0]
                        + fmaxf(d[mi][nt][3] + b2c[nt][1], 0.f) * w3c[nt][1];
                }
                v0 += __shfl_xor_sync(0xffffffffu, v0, 1);
                v0 += __shfl_xor_sync(0xffffffffu, v0, 2);
                v1 += __shfl_xor_sync(0xffffffffu, v1, 1);
                v1 += __shfl_xor_sync(0xffffffffu, v1, 2);
                if ((lane & 3) == 0) {
                    int r0 = mt * 16 + (lane >> 2);
                    part_sh[r0 * 8 + p]       = v0;
                    part_sh[(r0 + 8) * 8 + p] = v1;
                }
            }
        }
    }
    __syncthreads();

    if (tid < 160) {
        const float4* pr = (const float4*)(p2_sh + tid * 8);
        float4 u = pr[0], v = pr[1];
        logits[(size_t)bw * 160 + tid] =
            u.x + u.y + u.z + u.w + v.x + v.y + v.z + v.w + b3[0];
    }
}

// ---------------- finalize ----------------
__global__ __launch_bounds__(160) void finalize_kernel(
    const float* __restrict__ logits, const float* __restrict__ mask,
    float* __restrict__ out, int scalar_idx, int logits_off)
{
    int b = blockIdx.x;
    int k = threadIdx.x;
    float m = -3.4e38f;
    #pragma unroll
    for (int w = 0; w < Wc; w++) {
        size_t idx = (size_t)(b*Wc + w) * (Sc*Nc) + k;
        float v = logits[idx] + mask[idx];
        m = fmaxf(m, v);
    }
    out[b*(Sc*Nc) + k] = (m > 0.f) ? 1.f : 0.f;
    out[(size_t)logits_off + b*(Sc*Nc) + k] = m;
    if (b == 0 && k == 0 && scalar_idx >= 0) out[scalar_idx] = 160.0f;
}

// ---------------- host launcher ----------------
extern "C" void kernel_launch(void* const* d_in, const int* in_sizes, int n_in,
                              void* d_out, int out_size)
{
    const float* h    = (const float*)d_in[0];
    const float* c    = (const float*)d_in[1];
    const float* pos  = (const float*)d_in[3];
    const float* qst  = (const float*)d_in[4];
    const float* mask = (const float*)d_in[5];
    const float* wgt  = (const float*)d_in[6];
    const float* W1   = (const float*)d_in[7];
    const float* b1   = (const float*)d_in[8];
    const float* W2   = (const float*)d_in[9];
    const float* b2   = (const float*)d_in[10];
    const float* W3   = (const float*)d_in[11];
    const float* b3   = (const float*)d_in[12];
    float* out = (float*)d_out;

    float *qslot_p, *qw_p, *qslotw1_p, *qsw_p, *logits_p;
    cudaGetSymbolAddress((void**)&qslot_p,   g_qslot);
    cudaGetSymbolAddress((void**)&qw_p,      g_qw);
    cudaGetSymbolAddress((void**)&qslotw1_p, g_qslotW1);
    cudaGetSymbolAddress((void**)&qsw_p,     g_qsW);
    cudaGetSymbolAddress((void**)&logits_p,  g_logits);

    const int M_qs = Bc*Wc*Sc;   // 20480
    const int M_st = Bc*Wc*Nc;   // 8192

    cudaFuncSetAttribute(qslot_kernel,
        cudaFuncAttributeMaxDynamicSharedMemorySize, Q_SMEM);
    cudaFuncSetAttribute(fused_kernel,
        cudaFuncAttributeMaxDynamicSharedMemorySize, F_BYTES);

    gemm128_kernel<<<M_st/32, 256>>>(qst, W1 + 128*128, nullptr, qsw_p, qst);  // 1 (+ QS bf16 prep)
    qslot_kernel<<<Bc*Wc, 256, Q_SMEM>>>(h, c, pos, qslot_p, W2);              // 2 (+ W2^T bf16 prep)
    gemm_dual_kernel<<<M_qs/32, 256>>>(qslot_p, wgt, W1, b1, qw_p, qslotw1_p); // 3
    fused_kernel<<<Bc*Wc, 1024, F_BYTES>>>(                                    // 4  <-- profiled
        qw_p, qslotw1_p, qsw_p, b2, W3, b3, logits_p);

    int scalar_idx = (out_size == 2*Bc*Sc*Nc + 1) ? Bc*Sc*Nc : -1;
    int logits_off = out_size - Bc*Sc*Nc;
    finalize_kernel<<<Bc, 160>>>(logits_p, mask, out, scalar_idx, logits_off); // 5
}

// round 16
// speedup vs baseline: 1.3541x; 1.0614x over previous
#include <cuda_runtime.h>
#include <cuda_bf16.h>
#include <cstdint>
#include <math.h>

#define Bc 64
#define Wc 16
#define Tc 64
#define Uc 128
#define Sc 20
#define Nc 8
#define INF_ 100000.0f

// ---------------- scratch ----------------
__device__ float g_qslot[Bc*Wc*Sc*Uc];
__device__ float g_qw[Bc*Wc*Sc*Uc];
__device__ float g_qslotW1[Bc*Wc*Sc*Uc];
__device__ float g_qsW[Bc*Wc*Nc*Uc];
__device__ float g_logits[Bc*Wc*Sc*Nc];
__device__ __align__(16) __nv_bfloat16 g_W2Thi[16384];
__device__ __align__(16) __nv_bfloat16 g_W2Tlo[16384];
__device__ __align__(16) __nv_bfloat16 g_QShi[Bc*128*128];
__device__ __align__(16) __nv_bfloat16 g_QSlo[Bc*128*128];

__device__ __forceinline__ float2 pfma2(float2 a, float2 b, float2 c) {
    unsigned long long ua = *reinterpret_cast<unsigned long long*>(&a);
    unsigned long long ub = *reinterpret_cast<unsigned long long*>(&b);
    unsigned long long uc = *reinterpret_cast<unsigned long long*>(&c);
    unsigned long long ud;
    asm("fma.rn.f32x2 %0, %1, %2, %3;" : "=l"(ud) : "l"(ua), "l"(ub), "l"(uc));
    return *reinterpret_cast<float2*>(&ud);
}

__device__ __forceinline__ unsigned smem_u32_of(const void* p) {
    unsigned a;
    asm("{ .reg .u64 t; cvta.to.shared.u64 t, %1; cvt.u32.u64 %0, t; }" : "=r"(a) : "l"(p));
    return a;
}

__device__ __forceinline__ void mma16816(float* d, const unsigned* a, const unsigned* b) {
    asm volatile(
        "mma.sync.aligned.m16n8k16.row.col.f32.bf16.bf16.f32 "
        "{%0,%1,%2,%3}, {%4,%5,%6,%7}, {%8,%9}, {%0,%1,%2,%3};"
        : "+f"(d[0]), "+f"(d[1]), "+f"(d[2]), "+f"(d[3])
        : "r"(a[0]), "r"(a[1]), "r"(a[2]), "r"(a[3]), "r"(b[0]), "r"(b[1]));
}

__device__ __forceinline__ void ldsm_x4(unsigned* r, unsigned addr) {
    asm volatile("ldmatrix.sync.aligned.m8n8.x4.shared.b16 {%0,%1,%2,%3}, [%4];"
        : "=r"(r[0]), "=r"(r[1]), "=r"(r[2]), "=r"(r[3]) : "r"(addr));
}
__device__ __forceinline__ void ldsm_x2(unsigned* r, unsigned addr) {
    asm volatile("ldmatrix.sync.aligned.m8n8.x2.shared.b16 {%0,%1}, [%2];"
        : "=r"(r[0]), "=r"(r[1]) : "r"(addr));
}

// ---------------- merged prologue kernel: qslot (blocks 0..1023) + qsW gemm (1024..1279) ----------------
#define QP 132
#define Q_SMEM ((Tc*QP + Sc*QP + Sc*Tc) * 4)

__global__ __launch_bounds__(256) void prologue_kernel(
    const float* __restrict__ h, const float* __restrict__ c,
    const float* __restrict__ pos, float* __restrict__ qslot,
    const float* __restrict__ W2,
    const float* __restrict__ qstA, const float* __restrict__ W1bot,
    float* __restrict__ qswC, const float* __restrict__ qstatus)
{
    extern __shared__ float dyn[];
    int tid = threadIdx.x;

    if (blockIdx.x < 1024) {
        // ================= qslot body (proven) =================
        float* h_sh = dyn;
        float* c_sh = dyn + Tc*QP;
        float* p_sh = dyn + Tc*QP + Sc*QP;
        int bw = blockIdx.x;

        if (bw < 64) {
            int idx = bw * 256 + tid;
            int f = idx >> 7, k = idx & 127;
            float val = W2[(size_t)k * 128 + f];
            __nv_bfloat16 vhi = __float2bfloat16(val);
            __nv_bfloat16 vlo = __float2bfloat16(val - __bfloat162float(vhi));
            g_W2Thi[idx] = vhi;
            g_W2Tlo[idx] = vlo;
        }

        const float4* hb = (const float4*)(h + (size_t)bw * Tc * Uc);
        for (int i = tid; i < Tc*32; i += 256) {
            int r = i >> 5, c4 = i & 31;
            *(float4*)(h_sh + r*QP + 4*c4) = hb[i];
        }
        const float4* cg = (const float4*)c;
        for (int i = tid; i < Sc*32; i += 256) {
            int r = i >> 5, c4 = i & 31;
            *(float4*)(c_sh + r*QP + 4*c4) = cg[i];
        }
        __syncthreads();

        for (int task = tid; task < 320; task += 256) {
            int t = task & 63, sg = task >> 6;
            const float4* hr = (const float4*)(h_sh + t*QP);
            float2 pa[4];
            #pragma unroll
            for (int i = 0; i < 4; i++) pa[i] = make_float2(0.f, 0.f);
            #pragma unroll 8
            for (int u4 = 0; u4 < 32; u4++) {
                float4 hv = hr[u4];
                float2 hl = make_float2(hv.x, hv.y);
                float2 hh = make_float2(hv.z, hv.w);
                #pragma unroll
                for (int i = 0; i < 4; i++) {
                    float4 cv = *(const float4*)(c_sh + (4*sg+i)*QP + 4*u4);
                    pa[i] = pfma2(make_float2(cv.x, cv.y), hl, pa[i]);
                    pa[i] = pfma2(make_float2(cv.z, cv.w), hh, pa[i]);
                }
            }
            #pragma unroll
            for (int i = 0; i < 4; i++)
                p_sh[(4*sg+i)*Tc + t] = pa[i].x + pa[i].y;
        }
        __syncthreads();

        if (tid < Sc) {
            float* pr = p_sh + tid * Tc;
            float m = -3.4e38f;
            #pragma unroll
            for (int t = 0; t < Tc; t++) {
                float v = pr[t];
                if (v == 0.f) v = -INF_;
                pr[t] = v;
                m = fmaxf(m, v);
            }
            float sum = 0.f;
            #pragma unroll
            for (int t = 0; t < Tc; t++) { float e = expf(pr[t] - m); pr[t] = e; sum += e; }
            float r = 1.f / sum;
            #pragma unroll
            for (int t = 0; t < Tc; t++) pr[t] *= r;
        }
        __syncthreads();

        if (tid < 160) {
            int u4 = tid & 31, sg = tid >> 5;
            float2 aL[4], aH[4];
            #pragma unroll
            for (int i = 0; i < 4; i++) { aL[i] = make_float2(0.f, 0.f); aH[i] = make_float2(0.f, 0.f); }
            #pragma unroll 4
            for (int t = 0; t < Tc; t++) {
                float4 hv = *(const float4*)(h_sh + t*QP + 4*u4);
                float2 hl = make_float2(hv.x, hv.y);
                float2 hh = make_float2(hv.z, hv.w);
                #pragma unroll
                for (int i = 0; i < 4; i++) {
                    float p = p_sh[(4*sg+i)*Tc + t];
                    float2 pp = make_float2(p, p);
                    aL[i] = pfma2(pp, hl, aL[i]);
                    aH[i] = pfma2(pp, hh, aH[i]);
                }
            }
            const float* posb = pos + (size_t)bw * Sc * Uc;
            float* qb = qslot + (size_t)bw * Sc * Uc;
            #pragma unroll
            for (int i = 0; i < 4; i++) {
                int s = 4*sg + i;
                float4 pv = *(const float4*)(posb + s*128 + 4*u4);
                float4 o;
                o.x = aL[i].x + pv.x; o.y = aL[i].y + pv.y;
                o.z = aH[i].x + pv.z; o.w = aH[i].y + pv.w;
                *(float4*)(qb + s*128 + 4*u4) = o;
            }
        }
    } else {
        // ================= qsW gemm + QS bf16 convert body (proven) =================
        float* A_sh = dyn;                 // 32 x 33
        float* W_sh = dyn + 32*33;         // 32 x 128
        int blk = blockIdx.x - 1024;       // 0..255
        int row0 = blk * 32;
        int tx = tid & 31, ty = tid >> 5;
        int r0 = ty * 4, c0 = tx * 4;

        for (int i = blk * 256 + tid; i < Bc*128*128; i += 256*256) {
            float v = qstatus[i];
            __nv_bfloat16 vhi = __float2bfloat16(v);
            __nv_bfloat16 vlo = __float2bfloat16(v - __bfloat162float(vhi));
            g_QShi[i] = vhi;
            g_QSlo[i] = vlo;
        }

        float2 gacc[4][2];
        #pragma unroll
        for (int r = 0; r < 4; r++) {
            gacc[r][0] = make_float2(0.f, 0.f);
            gacc[r][1] = make_float2(0.f, 0.f);
        }

        for (int k0 = 0; k0 < 128; k0 += 32) {
            __syncthreads();
            #pragma unroll
            for (int rr = 0; rr < 32; rr += 8) {
                int r = rr + ty;
                A_sh[tx*33 + r] = qstA[(size_t)(row0 + r) * 128 + k0 + tx];
            }
            for (int i = tid; i < 32*128; i += 256)
                W_sh[i] = W1bot[(size_t)(k0 + (i >> 7)) * 128 + (i & 127)];
            __syncthreads();
            #pragma unroll
            for (int k = 0; k < 32; k++) {
                float4 w = *(const float4*)&W_sh[k*128 + c0];
                float2 wl = make_float2(w.x, w.y);
                float2 wh = make_float2(w.z, w.w);
                #pragma unroll
                for (int rr = 0; rr < 4; rr++) {
                    float a = A_sh[k*33 + r0 + rr];
                    float2 aa = make_float2(a, a);
                    gacc[rr][0] = pfma2(aa, wl, gacc[rr][0]);
                    gacc[rr][1] = pfma2(aa, wh, gacc[rr][1]);
                }
            }
        }
        #pragma unroll
        for (int rr = 0; rr < 4; rr++) {
            float4 o;
            o.x = gacc[rr][0].x; o.y = gacc[rr][0].y;
            o.z = gacc[rr][1].x; o.w = gacc[rr][1].y;
            *(float4*)&qswC[(size_t)(row0 + r0 + rr) * 128 + c0] = o;
        }
    }
}

// ---------------- dual-output GEMM (proven) ----------------
#define DA_PITCH 34
__global__ __launch_bounds__(256) void gemm_dual_kernel(
    const float* __restrict__ A,
    const float* __restrict__ Wa, const float* __restrict__ Wb,
    const float* __restrict__ biasB,
    float* __restrict__ Ca, float* __restrict__ Cb)
{
    __shared__ float  A_sh[32*DA_PITCH];
    __shared__ float2 Wi[2*16*128];

    int tid  = threadIdx.x;
    int row0 = blockIdx.x * 32;
    int tx = tid & 31, ty = tid >> 5;
    int c0 = tx * 4;
    int r0 = ty * 4;

    float2 dacc[2][4][4];
    #pragma unroll
    for (int m = 0; m < 2; m++)
        #pragma unroll
        for (int r = 0; r < 4; r++)
            #pragma unroll
            for (int cc = 0; cc < 4; cc++) dacc[m][r][cc] = make_float2(0.f, 0.f);

    for (int k0 = 0; k0 < 128; k0 += 32) {
        __syncthreads();
        #pragma unroll
        for (int i = 0; i < 4; i++) {
            int r = ty + 8*i;
            A_sh[r*DA_PITCH + tx] = A[(size_t)(row0 + r) * 128 + k0 + tx];
        }
        #pragma unroll
        for (int i = 0; i < 16; i++) {
            int idx = tid + 256*i;
            int m = idx >> 11, kp = (idx >> 7) & 15, cc = idx & 127;
            const float* W = m ? Wb : Wa;
            Wi[idx] = make_float2(W[(size_t)(k0 + 2*kp) * 128 + cc],
                                  W[(size_t)(k0 + 2*kp + 1) * 128 + cc]);
        }
        __syncthreads();

        #pragma unroll 4
        for (int kp = 0; kp < 16; kp++) {
            float2 ar[4];
            #pragma unroll
            for (int r = 0; r < 4; r++)
                ar[r] = *(const float2*)(A_sh + (r0 + r)*DA_PITCH + 2*kp);

            float2 uwa[4], uwb[4];
            {
                const float4* wa4 = (const float4*)(Wi + kp*128 + c0);
                const float4* wb4 = (const float4*)(Wi + 2048 + kp*128 + c0);
                float4 waA = wa4[0];
                float4 waB = wa4[1];
                float4 wbA = wb4[0];
                float4 wbB = wb4[1];
                uwa[0] = make_float2(waA.x, waA.y);
                uwa[1] = make_float2(waA.z, waA.w);
                uwa[2] = make_float2(waB.x, waB.y);
                uwa[3] = make_float2(waB.z, waB.w);
                uwb[0] = make_float2(wbA.x, wbA.y);
                uwb[1] = make_float2(wbA.z, wbA.w);
                uwb[2] = make_float2(wbB.x, wbB.y);
                uwb[3] = make_float2(wbB.z, wbB.w);
            }

            #pragma unroll
            for (int r = 0; r < 4; r++) {
                #pragma unroll
                for (int cc = 0; cc < 4; cc++) {
                    dacc[0][r][cc] = pfma2(ar[r], uwa[cc], dacc[0][r][cc]);
                    dacc[1][r][cc] = pfma2(ar[r], uwb[cc], dacc[1][r][cc]);
                }
            }
        }
    }

    float bb[4];
    #pragma unroll
    for (int cc = 0; cc < 4; cc++) bb[cc] = biasB[c0 + cc];
    #pragma unroll
    for (int r = 0; r < 4; r++) {
        int row = row0 + r0 + r;
        float4 oa, ob;
        oa.x = dacc[0][r][0].x + dacc[0][r][0].y;
        oa.y = dacc[0][r][1].x + dacc[0][r][1].y;
        oa.z = dacc[0][r][2].x + dacc[0][r][2].y;
        oa.w = dacc[0][r][3].x + dacc[0][r][3].y;
        ob.x = dacc[1][r][0].x + dacc[1][r][0].y + bb[0];
        ob.y = dacc[1][r][1].x + dacc[1][r][1].y + bb[1];
        ob.z = dacc[1][r][2].x + dacc[1][r][2].y + bb[2];
        ob.w = dacc[1][r][3].x + dacc[1][r][3].y + bb[3];
        *(float4*)&Ca[(size_t)row*128 + c0] = oa;
        *(float4*)&Cb[(size_t)row*128 + c0] = ob;
    }
}

// ---------------- fused kernel (R16, proven): 1024 threads, smem LDSM, ks-outer layer2 ----------------
#define PITCHB 272
#define W2T_HI 0
#define W2T_LO 34816
#define H1_HI  69632
#define H1_LO  113152
#define QS_HI  69632
#define QS_LO  113152
#define QWB_HI 156672
#define QWB_LO 165376
#define CO_B   174080
#define P2_B   190464
#define BW_B   200704
#define F_BYTES 201728

__global__ __launch_bounds__(1024, 1) void fused_kernel(
    const float* __restrict__ qw, const float* __restrict__ q1,
    const float* __restrict__ qsw,
    const float* __restrict__ b2, const float* __restrict__ W3,
    const float* __restrict__ b3, float* __restrict__ logits)
{
    extern __shared__ float sm[];
    unsigned base_u = smem_u32_of(sm);
    char* basep = (char*)sm;

    float* p2_sh = (float*)(basep + P2_B);
    float* bw_sh = (float*)(basep + BW_B);
    float* co_sh = (float*)(basep + CO_B);

    int bw = blockIdx.x;
    int b  = bw >> 4;
    int tid = threadIdx.x;

    {
        const float4* s1 = (const float4*)g_W2Thi;
        const float4* s2 = (const float4*)g_W2Tlo;
        const float4* s3 = (const float4*)(g_QShi + (size_t)b * 16384);
        const float4* s4 = (const float4*)(g_QSlo + (size_t)b * 16384);
        for (int i = tid; i < 2048; i += 1024) {
            int f = i >> 4, k4 = i & 15;
            *(float4*)(basep + W2T_HI + f*PITCHB + k4*16) = s1[i];
            *(float4*)(basep + W2T_LO + f*PITCHB + k4*16) = s2[i];
            *(float4*)(basep + QS_HI  + f*PITCHB + k4*16) = s3[i];
            *(float4*)(basep + QS_LO  + f*PITCHB + k4*16) = s4[i];
        }
    }
    {
        const float* qwb = qw + (size_t)bw * 2560;
        for (int i = tid; i < 2048; i += 1024) {
            int row = i >> 6, kp = i & 63;
            __nv_bfloat162 hp, lp;
            if (row < Sc) {
                float2 v = *(const float2*)(qwb + row * 128 + 2*kp);
                __nv_bfloat16 hx = __float2bfloat16(v.x);
                __nv_bfloat16 hy = __float2bfloat16(v.y);
                hp.x = hx; hp.y = hy;
                lp.x = __float2bfloat16(v.x - __bfloat162float(hx));
                lp.y = __float2bfloat16(v.y - __bfloat162float(hy));
            } else {
                hp.x = __float2bfloat16(0.f); hp.y = hp.x;
                lp.x = hp.x; lp.y = hp.x;
            }
            *(unsigned*)(basep + QWB_HI + row*PITCHB + kp*4) = *(unsigned*)&hp;
            *(unsigned*)(basep + QWB_LO + row*PITCHB + kp*4) = *(unsigned*)&lp;
        }
    }
    if (tid < 128) bw_sh[tid] = b2[tid];
    else if (tid < 256) bw_sh[tid] = W3[tid - 128];
    __syncthreads();

    {
        int lane = tid & 31;
        int wrp  = tid >> 5;
        int mt   = wrp >> 4;
        int np   = wrp & 15;

        unsigned a_hi = base_u + (unsigned)(QWB_HI + (lane & 15) * PITCHB
                      + (lane >> 4) * 16 + mt * 16 * PITCHB);
        unsigned a_lo = a_hi + (unsigned)(QWB_LO - QWB_HI);
        unsigned baddr = base_u + (unsigned)(QS_HI
                       + (8*np + (lane & 7)) * PITCHB + ((lane >> 3) & 1) * 16);
        unsigned baddr_lo = baddr + (unsigned)(QS_LO - QS_HI);

        float d[4] = {0.f, 0.f, 0.f, 0.f};
        #pragma unroll
        for (int ks = 0; ks < 8; ks++) {
            unsigned ah[4], al[4], bh[2], bl[2];
            ldsm_x4(ah, a_hi + ks*32);
            ldsm_x4(al, a_lo + ks*32);
            ldsm_x2(bh, baddr + ks*32);
            ldsm_x2(bl, baddr_lo + ks*32);
            mma16816(d, ah, bh);
            mma16816(d, ah, bl);
            mma16816(d, al, bh);
            mma16816(d, al, bl);
        }
        int r0 = mt * 16 + (lane >> 2);
        int c0 = 8*np + 2*(lane & 3);
        co_sh[r0 * 128 + c0]           = d[0];
        co_sh[r0 * 128 + c0 + 1]       = d[1];
        co_sh[(r0 + 8) * 128 + c0]     = d[2];
        co_sh[(r0 + 8) * 128 + c0 + 1] = d[3];
    }
    __syncthreads();

    if (tid < Sc * Nc) {
        int s = tid >> 3, n = tid & 7;
        float vals[16];
        float m = -3.4e38f;
        #pragma unroll
        for (int x = 0; x < 16; x++) {
            float v = co_sh[s * 128 + x * 8 + n];
            if (v == 0.f) v = -INF_;
            vals[x] = v;
            m = fmaxf(m, v);
        }
        float sum = 0.f;
        #pragma unroll
        for (int x = 0; x < 16; x++) { float e = expf(vals[x] - m); vals[x] = e; sum += e; }
        float rs = 1.f / sum;
        #pragma unroll
        for (int x = 0; x < 16; x++)
            p2_sh[n * 320 + s * 16 + x] = vals[x] * rs;
    }
    __syncthreads();

    {
        int n  = tid >> 7;
        int sh = (tid >> 6) & 1;
        int u2 = tid & 63;
        const float* qswb = qsw + ((size_t)b * Wc * Nc + n) * Uc + 2 * u2;
        float2 qv[16];
        #pragma unroll
        for (int x = 0; x < 16; x++)
            qv[x] = *(const float2*)(qswb + (size_t)x * Nc * Uc);

        const float* q1b = q1 + (size_t)bw * 2560;
        const float4* pp_base = (const float4*)(p2_sh + n * 320);
        char* hhi = basep + H1_HI;
        char* hlo = basep + H1_LO;

        #pragma unroll
        for (int si = 0; si < 10; si++) {
            int s = sh * 10 + si;
            float4 p0 = pp_base[s*4 + 0];
            float4 p1 = pp_base[s*4 + 1];
            float4 p2v = pp_base[s*4 + 2];
            float4 p3 = pp_base[s*4 + 3];
            float2 a = make_float2(0.f, 0.f);
            a = pfma2(make_float2(p0.x, p0.x), qv[0],  a);
            a = pfma2(make_float2(p0.y, p0.y), qv[1],  a);
            a = pfma2(make_float2(p0.z, p0.z), qv[2],  a);
            a = pfma2(make_float2(p0.w, p0.w), qv[3],  a);
            a = pfma2(make_float2(p1.x, p1.x), qv[4],  a);
            a = pfma2(make_float2(p1.y, p1.y), qv[5],  a);
            a = pfma2(make_float2(p1.z, p1.z), qv[6],  a);
            a = pfma2(make_float2(p1.w, p1.w), qv[7],  a);
            a = pfma2(make_float2(p2v.x, p2v.x), qv[8],  a);
            a = pfma2(make_float2(p2v.y, p2v.y), qv[9],  a);
            a = pfma2(make_float2(p2v.z, p2v.z), qv[10], a);
            a = pfma2(make_float2(p2v.w, p2v.w), qv[11], a);
            a = pfma2(make_float2(p3.x, p3.x), qv[12], a);
            a = pfma2(make_float2(p3.y, p3.y), qv[13], a);
            a = pfma2(make_float2(p3.z, p3.z), qv[14], a);
            a = pfma2(make_float2(p3.w, p3.w), qv[15], a);

            float2 base = *(const float2*)(q1b + s * 128 + 2 * u2);
            float hx = fmaxf(a.x + base.x, 0.f);
            float hy = fmaxf(a.y + base.y, 0.f);

            __nv_bfloat16 bhx = __float2bfloat16(hx);
            __nv_bfloat16 bhy = __float2bfloat16(hy);
            __nv_bfloat16 blx = __float2bfloat16(hx - __bfloat162float(bhx));
            __nv_bfloat16 bly = __float2bfloat16(hy - __bfloat162float(bhy));
            __nv_bfloat162 hp;
            hp.x = bhx; hp.y = bhy;
            __nv_bfloat162 lp;
            lp.x = blx; lp.y = bly;

            int row = s * 8 + n;
            *(unsigned*)(hhi + row*PITCHB + u2*4) = *(unsigned*)&hp;
            *(unsigned*)(hlo + row*PITCHB + u2*4) = *(unsigned*)&lp;
        }
    }
    __syncthreads();

    {
        int lane = tid & 31;
        int wrp  = tid >> 5;
        int g    = wrp >> 3;
        int p    = wrp & 7;
        int mcnt = (g < 2) ? 3 : 2;
        int mst  = (g < 2) ? 3*g : 6 + 2*(g - 2);

        unsigned bbase[2];
        #pragma unroll
        for (int nt = 0; nt < 2; nt++)
            bbase[nt] = base_u + (unsigned)(W2T_HI
                      + (16*p + 8*nt + (lane & 7)) * PITCHB
                      + ((lane >> 3) & 1) * 16);

        unsigned abase_hi = base_u + (unsigned)(H1_HI + (lane & 15) * PITCHB + (lane >> 4) * 16);
        unsigned abase_lo = abase_hi + (unsigned)(H1_LO - H1_HI);
        float* part_sh = p2_sh;

        float d[3][2][4];
        #pragma unroll
        for (int mi = 0; mi < 3; mi++)
            #pragma unroll
            for (int nt = 0; nt < 2; nt++)
                #pragma unroll
                for (int j = 0; j < 4; j++) d[mi][nt][j] = 0.f;

        #pragma unroll
        for (int ks = 0; ks < 8; ks++) {
            unsigned bh[2][2], bl[2][2];
            #pragma unroll
            for (int nt = 0; nt < 2; nt++) {
                ldsm_x2(bh[nt], bbase[nt] + ks*32);
                ldsm_x2(bl[nt], bbase[nt] + (unsigned)(W2T_LO - W2T_HI) + ks*32);
            }
            #pragma unroll
            for (int mi = 0; mi < 3; mi++) {
                if (mi < mcnt) {
                    int mt = mst + mi;
                    unsigned ah[4], alr[4];
                    ldsm_x4(ah,  abase_hi + (unsigned)(mt * 16 * PITCHB) + ks*32);
                    ldsm_x4(alr, abase_lo + (unsigned)(mt * 16 * PITCHB) + ks*32);
                    #pragma unroll
                    for (int nt = 0; nt < 2; nt++) {
                        mma16816(d[mi][nt], ah,  bh[nt]);
                        mma16816(d[mi][nt], ah,  bl[nt]);
                        mma16816(d[mi][nt], alr, bh[nt]);
                    }
                }
            }
        }

        float b2c[2][2], w3c[2][2];
        #pragma unroll
        for (int nt = 0; nt < 2; nt++) {
            int c0 = 16*p + 8*nt + 2*(lane & 3);
            b2c[nt][0] = bw_sh[c0];       b2c[nt][1] = bw_sh[c0+1];
            w3c[nt][0] = bw_sh[128+c0];   w3c[nt][1] = bw_sh[128+c0+1];
        }

        #pragma unroll
        for (int mi = 0; mi < 3; mi++) {
            if (mi < mcnt) {
                int mt = mst + mi;
                float v0 = 0.f, v1 = 0.f;
                #pragma unroll
                for (int nt = 0; nt < 2; nt++) {
                    v0 += fmaxf(d[mi][nt][0] + b2c[nt][0], 0.f) * w3c[nt][0]
                        + fmaxf(d[mi][nt][1] + b2c[nt][1], 0.f) * w3c[nt][1];
                    v1 += fmaxf(d[mi][nt][2] + b2c[nt][0], 0.f) * w3c[nt][0]
                        + fmaxf(d[mi][nt][3] + b2c[nt][1], 0.f) * w3c[nt][1];
                }
                v0 += __shfl_xor_sync(0xffffffffu, v0, 1);
                v0 += __shfl_xor_sync(0xffffffffu, v0, 2);
                v1 += __shfl_xor_sync(0xffffffffu, v1, 1);
                v1 += __shfl_xor_sync(0xffffffffu, v1, 2);
                if ((lane & 3) == 0) {
                    int r0 = mt * 16 + (lane >> 2);
                    part_sh[r0 * 8 + p]       = v0;
                    part_sh[(r0 + 8) * 8 + p] = v1;
                }
            }
        }
    }
    __syncthreads();

    if (tid < 160) {
        const float4* pr = (const float4*)(p2_sh + tid * 8);
        float4 u = pr[0], v = pr[1];
        logits[(size_t)bw * 160 + tid] =
            u.x + u.y + u.z + u.w + v.x + v.y + v.z + v.w + b3[0];
    }
}

// ---------------- finalize ----------------
__global__ __launch_bounds__(160) void finalize_kernel(
    const float* __restrict__ logits, const float* __restrict__ mask,
    float* __restrict__ out, int scalar_idx, int logits_off)
{
    int b = blockIdx.x;
    int k = threadIdx.x;
    float m = -3.4e38f;
    #pragma unroll
    for (int w = 0; w < Wc; w++) {
        size_t idx = (size_t)(b*Wc + w) * (Sc*Nc) + k;
        float v = logits[idx] + mask[idx];
        m = fmaxf(m, v);
    }
    out[b*(Sc*Nc) + k] = (m > 0.f) ? 1.f : 0.f;
    out[(size_t)logits_off + b*(Sc*Nc) + k] = m;
    if (b == 0 && k == 0 && scalar_idx >= 0) out[scalar_idx] = 160.0f;
}

// ---------------- host launcher ----------------
extern "C" void kernel_launch(void* const* d_in, const int* in_sizes, int n_in,
                              void* d_out, int out_size)
{
    const float* h    = (const float*)d_in[0];
    const float* c    = (const float*)d_in[1];
    const float* pos  = (const float*)d_in[3];
    const float* qst  = (const float*)d_in[4];
    const float* mask = (const float*)d_in[5];
    const float* wgt  = (const float*)d_in[6];
    const float* W1   = (const float*)d_in[7];
    const float* b1   = (const float*)d_in[8];
    const float* W2   = (const float*)d_in[9];
    const float* b2   = (const float*)d_in[10];
    const float* W3   = (const float*)d_in[11];
    const float* b3   = (const float*)d_in[12];
    float* out = (float*)d_out;

    float *qslot_p, *qw_p, *qslotw1_p, *qsw_p, *logits_p;
    cudaGetSymbolAddress((void**)&qslot_p,   g_qslot);
    cudaGetSymbolAddress((void**)&qw_p,      g_qw);
    cudaGetSymbolAddress((void**)&qslotw1_p, g_qslotW1);
    cudaGetSymbolAddress((void**)&qsw_p,     g_qsW);
    cudaGetSymbolAddress((void**)&logits_p,  g_logits);

    const int M_qs = Bc*Wc*Sc;   // 20480

    cudaFuncSetAttribute(prologue_kernel,
        cudaFuncAttributeMaxDynamicSharedMemorySize, Q_SMEM);
    cudaFuncSetAttribute(fused_kernel,
        cudaFuncAttributeMaxDynamicSharedMemorySize, F_BYTES);

    // merged: qslot (1024 blocks) + qsW gemm & QS convert (256 blocks)
    prologue_kernel<<<1280, 256, Q_SMEM>>>(
        h, c, pos, qslot_p, W2, qst, W1 + 128*128, qsw_p, qst);               // 1
    gemm_dual_kernel<<<M_qs/32, 256>>>(qslot_p, wgt, W1, b1, qw_p, qslotw1_p); // 2
    fused_kernel<<<Bc*Wc, 1024, F_BYTES>>>(                                    // 3
        qw_p, qslotw1_p, qsw_p, b2, W3, b3, logits_p);
    finalize_kernel<<<Bc, 160>>>(logits_p, mask, out,
        (out_size == 2*Bc*Sc*Nc + 1) ? Bc*Sc*Nc : -1, out_size - Bc*Sc*Nc);    // 4
}